// round 8
// baseline (speedup 1.0000x reference)
#include <cuda_runtime.h>
#include <math.h>

#define T    32
#define Bz   32
#define NIN  512
#define NH   1024
#define NOUT 256
#define NBLK 128      // uniform grid: 8 k-slices x 16 j-tiles
#define NTH  256

// ---------------- persistent state (device globals; no allocation) ----------
__device__ float dS[T * Bz * NH];       // relu(relu(x)@W_i)      [m=(t,b)][k]
__device__ float dZ[T * Bz * NH];       // relu(S@W_z)            [m][k]
__device__ float dZCt[T * NH * Bz];     // Z@W_c transposed       [t][j][b]
__device__ float dHistAcc[T * NH * Bz]; // PRE-relu h accumulators [t][j][b]
__device__ float dHsAcc[NH * Bz];       // hs accumulator (zc + Ht@Wh)
__device__ float dHcur[NH * Bz];        // post-norm carry        [j][b]
__device__ float dOt[NH * Bz];          // o accumulator (pre-relu)
__device__ float dDotsRaw[T * Bz];      // raw dot accumulators [tau][b]
// tree barrier (monotonic counters; zero-init once; graph-replay safe)
__device__ unsigned gLeaf[16 * 32];     // 16 counters, one per 128B line
__device__ unsigned gRoot;
__device__ volatile unsigned gEpoch;

// ---------------- packed f32x2 helpers --------------------------------------
static __device__ __forceinline__ unsigned long long pk2(float v) {
    unsigned long long r;
    asm("mov.b64 %0, {%1, %1};" : "=l"(r) : "f"(v));
    return r;
}
static __device__ __forceinline__ void ffma2(unsigned long long& d,
                                             unsigned long long a,
                                             unsigned long long b) {
    asm("fma.rn.f32x2 %0, %1, %2, %0;" : "+l"(d) : "l"(a), "l"(b));
}
static __device__ __forceinline__ float2 up2(unsigned long long v) {
    float2 f;
    asm("mov.b64 {%0, %1}, %2;" : "=f"(f.x), "=f"(f.y) : "l"(v));
    return f;
}

// ---------------- tree grid barrier (128 CTAs: 16 groups of 8) --------------
__device__ __forceinline__ void gsync() {
    __syncthreads();
    if (threadIdx.x == 0) {
        __threadfence();
        unsigned e = gEpoch;
        if ((atomicAdd(&gLeaf[((unsigned)blockIdx.x >> 3) << 5], 1u) & 7u) == 7u) {
            if ((atomicAdd(&gRoot, 1u) & 15u) == 15u) {
                __threadfence();
                atomicAdd((unsigned*)&gEpoch, 1u);
            }
        }
        while (gEpoch == e) {}
        __threadfence();
    }
    __syncthreads();
}

// ---------------- big GEMM (precompute): C[M,N] = op(A[M,K] @ W[K,N]) -------
template <bool RIN, bool ROUT, bool TST>
__device__ __forceinline__ void gemm_big_dev(const float* __restrict__ A,
                                             const float* __restrict__ W,
                                             float* __restrict__ C,
                                             int M, int N, int K) {
    __shared__ __align__(16) float As[2][16][64];
    __shared__ __align__(16) float Bs[2][16][64];
    int tid = threadIdx.x;
    int tx = tid & 15, ty = tid >> 4;
    int tilesN = N >> 6;
    int m0 = (blockIdx.x / tilesN) << 6;
    int n0 = (blockIdx.x % tilesN) << 6;

    int ra = tid >> 2, ca = (tid & 3) << 2;
    int rb = tid >> 4, cb = (tid & 15) << 2;
    const float* Ap = A + (size_t)(m0 + ra) * K + ca;
    const float* Wp = W + (size_t)rb * N + n0 + cb;

    unsigned long long acc[4][2];
#pragma unroll
    for (int i = 0; i < 4; i++) { acc[i][0] = 0ull; acc[i][1] = 0ull; }

    int nch = K >> 4;
    {
        float4 va = *reinterpret_cast<const float4*>(Ap);
        if (RIN) {
            va.x = fmaxf(va.x, 0.f); va.y = fmaxf(va.y, 0.f);
            va.z = fmaxf(va.z, 0.f); va.w = fmaxf(va.w, 0.f);
        }
        float4 vb = *reinterpret_cast<const float4*>(Wp);
        As[0][ca + 0][ra] = va.x; As[0][ca + 1][ra] = va.y;
        As[0][ca + 2][ra] = va.z; As[0][ca + 3][ra] = va.w;
        *reinterpret_cast<float4*>(&Bs[0][rb][cb]) = vb;
    }
    __syncthreads();

    for (int ch = 0; ch < nch; ch++) {
        int cur = ch & 1;
        float4 va, vb;
        if (ch + 1 < nch) {
            va = *reinterpret_cast<const float4*>(Ap + (ch + 1) * 16);
            vb = *reinterpret_cast<const float4*>(Wp + (size_t)(ch + 1) * 16 * N);
            if (RIN) {
                va.x = fmaxf(va.x, 0.f); va.y = fmaxf(va.y, 0.f);
                va.z = fmaxf(va.z, 0.f); va.w = fmaxf(va.w, 0.f);
            }
        }
#pragma unroll
        for (int k = 0; k < 16; k++) {
            float4 a4 = *reinterpret_cast<float4*>(&As[cur][k][ty * 4]);
            ulonglong2 b2 = *reinterpret_cast<ulonglong2*>(&Bs[cur][k][tx * 4]);
            unsigned long long a0 = pk2(a4.x), a1 = pk2(a4.y);
            unsigned long long a2 = pk2(a4.z), a3 = pk2(a4.w);
            ffma2(acc[0][0], a0, b2.x); ffma2(acc[0][1], a0, b2.y);
            ffma2(acc[1][0], a1, b2.x); ffma2(acc[1][1], a1, b2.y);
            ffma2(acc[2][0], a2, b2.x); ffma2(acc[2][1], a2, b2.y);
            ffma2(acc[3][0], a3, b2.x); ffma2(acc[3][1], a3, b2.y);
        }
        if (ch + 1 < nch) {
            int nxt = cur ^ 1;
            As[nxt][ca + 0][ra] = va.x; As[nxt][ca + 1][ra] = va.y;
            As[nxt][ca + 2][ra] = va.z; As[nxt][ca + 3][ra] = va.w;
            *reinterpret_cast<float4*>(&Bs[nxt][rb][cb]) = vb;
        }
        __syncthreads();
    }
#pragma unroll
    for (int i = 0; i < 4; i++) {
        float2 u0 = up2(acc[i][0]);
        float2 u1 = up2(acc[i][1]);
        float vals[4] = {u0.x, u0.y, u1.x, u1.y};
#pragma unroll
        for (int j = 0; j < 4; j++) {
            float v = vals[j];
            if (ROUT) v = fmaxf(v, 0.f);
            int m = m0 + ty * 4 + i;
            int n = n0 + tx * 4 + j;
            if (TST) {
                C[(((size_t)(m >> 5) * NH) + n) * Bz + (m & 31)] = v;  // [t][n][b]
            } else {
                C[(size_t)m * N + n] = v;
            }
        }
    }
}

__global__ void __launch_bounds__(256) k_gemm_s(const float* __restrict__ x,
                                                const float* __restrict__ Wi) {
    gemm_big_dev<true, true, false>(x, Wi, dS, T * Bz, NH, NIN);
}
__global__ void __launch_bounds__(256) k_gemm_z(const float* __restrict__ Wz) {
    gemm_big_dev<false, true, false>(dS, Wz, dZ, T * Bz, NH, NH);
}
__global__ void __launch_bounds__(256) k_gemm_zc(const float* __restrict__ Wc) {
    gemm_big_dev<false, false, true>(dZ, Wc, dZCt, T * Bz, NH, NH);
}

// ---------------- persistent recurrence kernel ------------------------------
// CTA bx: jt = bx&15 (j0 = jt*64), ks = bx>>4 (k0 = ks*128).
// smem (dynamic, 64 KB): resident W slice [128][64] + duplicated A [128][64].
struct SmemT {
    float Ws[128][64];    // 32 KB  (W[k][j])
    float As2[128][64];   // 32 KB  (A duplicated: As2[k][2b]=As2[k][2b+1]=h[k][b])
};

__device__ __forceinline__ void load_wslice(SmemT* sm, const float* __restrict__ W,
                                            int k0, int j0, int ldw) {
    int tid = threadIdx.x;
#pragma unroll
    for (int i = 0; i < 8; i++) {
        int e = (tid + i * NTH) * 4;
        int r = e >> 6, c = e & 63;
        *reinterpret_cast<float4*>(&sm->Ws[r][c]) =
            *reinterpret_cast<const float4*>(W + (size_t)(k0 + r) * ldw + j0 + c);
    }
}

// stage a [128][32] slice from global into duplicated smem As2 (optional relu)
template <bool RELU>
__device__ __forceinline__ void load_aslice_dup(SmemT* sm, const float* __restrict__ src) {
    int tid = threadIdx.x;
    const float4* s = reinterpret_cast<const float4*>(src);
#pragma unroll
    for (int i = 0; i < 4; i++) {
        int idx = tid + i * NTH;       // float4 index over 1024
        float4 v = s[idx];
        if (RELU) {
            v.x = fmaxf(v.x, 0.f); v.y = fmaxf(v.y, 0.f);
            v.z = fmaxf(v.z, 0.f); v.w = fmaxf(v.w, 0.f);
        }
        int k = idx >> 3, bq = idx & 7;
        float4 lo = {v.x, v.x, v.y, v.y};
        float4 hi = {v.z, v.z, v.w, v.w};
        *reinterpret_cast<float4*>(&sm->As2[k][bq * 8])     = lo;
        *reinterpret_cast<float4*>(&sm->As2[k][bq * 8 + 4]) = hi;
    }
}

// core GEMM over resident tiles: 4b x 4j per thread, 2-way k-split by tid>>7
__device__ __forceinline__ void gemm_core(SmemT* sm, unsigned long long acc[4][2]) {
    int tid = threadIdx.x;
    int half = tid >> 7;
    int r = tid & 127;
    int jg = r & 15;      // j group of 4
    int bg = r >> 4;      // b group of 4 (0..7)
    const float* wsr = &sm->Ws[half << 6][jg * 4];
    const float* asr = &sm->As2[half << 6][bg * 8];
#pragma unroll 8
    for (int k = 0; k < 64; k++) {
        ulonglong2 w2  = *reinterpret_cast<const ulonglong2*>(wsr);
        ulonglong2 a01 = *reinterpret_cast<const ulonglong2*>(asr);
        ulonglong2 a23 = *reinterpret_cast<const ulonglong2*>(asr + 4);
        ffma2(acc[0][0], a01.x, w2.x); ffma2(acc[0][1], a01.x, w2.y);
        ffma2(acc[1][0], a01.y, w2.x); ffma2(acc[1][1], a01.y, w2.y);
        ffma2(acc[2][0], a23.x, w2.x); ffma2(acc[2][1], a23.x, w2.y);
        ffma2(acc[3][0], a23.y, w2.x); ffma2(acc[3][1], a23.y, w2.y);
        wsr += 64; asr += 64;
    }
}

// GEMM + reduction via RED.ADD.F32 into dst[j*Bz + b] (dst pre-initialized)
__device__ __forceinline__ void slice_gemm_red(SmemT* sm, float* __restrict__ dst,
                                               int j0) {
    unsigned long long acc[4][2];
#pragma unroll
    for (int i = 0; i < 4; i++) { acc[i][0] = 0ull; acc[i][1] = 0ull; }
    gemm_core(sm, acc);
    int r = threadIdx.x & 127;
    int jj = j0 + (r & 15) * 4;
    int b0 = (r >> 4) * 4;
#pragma unroll
    for (int bb = 0; bb < 4; bb++) {
        float2 u0 = up2(acc[bb][0]);
        float2 u1 = up2(acc[bb][1]);
        atomicAdd(&dst[(size_t)(jj + 0) * Bz + b0 + bb], u0.x);
        atomicAdd(&dst[(size_t)(jj + 1) * Bz + b0 + bb], u0.y);
        atomicAdd(&dst[(size_t)(jj + 2) * Bz + b0 + bb], u1.x);
        atomicAdd(&dst[(size_t)(jj + 3) * Bz + b0 + bb], u1.y);
    }
}

__global__ void __launch_bounds__(NTH, 1)
memnet_rec_kernel(const float* __restrict__ Wh,  const float* __restrict__ Who,
                  const float* __restrict__ Wo,  const float* __restrict__ lam_p,
                  const float* __restrict__ eta_p, const float* __restrict__ g_p,
                  const float* __restrict__ b_p, float* __restrict__ out) {
    extern __shared__ __align__(16) char smembuf[];
    SmemT* sm = reinterpret_cast<SmemT*>(smembuf);
    int bx   = blockIdx.x;
    int tid  = threadIdx.x;
    int lane = tid & 31;
    int w    = tid >> 5;
    int jt = bx & 15, ks = bx >> 4;
    int j0 = jt << 6, k0 = ks << 7;

    // ---- pre-loop init: HistAcc[0] = zc[0], HsAcc = zc[0], dots = 0 --------
    {
        int i = bx * NTH + tid;
        if (i < NH * Bz / 4) {
            float4 z = reinterpret_cast<const float4*>(dZCt)[i];
            reinterpret_cast<float4*>(dHistAcc)[i] = z;
            reinterpret_cast<float4*>(dHsAcc)[i] = z;
        }
        if (bx == 0) {
            float4 zz = {0.f, 0.f, 0.f, 0.f};
            reinterpret_cast<float4*>(dDotsRaw)[tid] = zz;
        }
    }
    load_wslice(sm, Wh, k0, j0, NH);
    gsync();

    const float lam = lam_p[0];
    const float eta = eta_p[0];

    for (int t = 0; t < T; t++) {
        float* hAcc = dHistAcc + (size_t)t * NH * Bz;

        // ---- Phase A (t>0): RED h_prev @ W_h into HistAcc[t]; zero dots ----
        if (t > 0) {
            load_aslice_dup<false>(sm, dHcur + (size_t)k0 * Bz);
            if (bx == 0) {
                float4 zz = {0.f, 0.f, 0.f, 0.f};
                reinterpret_cast<float4*>(dDotsRaw)[tid] = zz;
            }
            __syncthreads();
            slice_gemm_red(sm, hAcc, j0);
            gsync();
        }

        // ---- Phase B: relu(HistAcc[t]) slice -> smem; dots; RED into HsAcc -
        {
            load_aslice_dup<true>(sm, hAcc + (size_t)k0 * Bz);
            __syncthreads();

            // dots: this CTA handles tau = jt, jt+16 (<= t) over its k-slice
            for (int tau = jt; tau <= t; tau += 16) {
                float a = 0.f;
                int kb = w << 4;
                if (tau == t) {
#pragma unroll
                    for (int kk = 0; kk < 16; kk++) {
                        float xv = sm->As2[kb + kk][lane * 2];
                        a += xv * xv;
                    }
                } else {
                    const float* Hs = dHistAcc + (size_t)tau * NH * Bz + (size_t)k0 * Bz;
#pragma unroll
                    for (int kk = 0; kk < 16; kk++)
                        a += sm->As2[kb + kk][lane * 2]
                           * fmaxf(Hs[(kb + kk) * Bz + lane], 0.f);
                }
                atomicAdd(&dDotsRaw[tau * Bz + lane], a);
            }

            slice_gemm_red(sm, dHsAcc, j0);
        }
        gsync();

        // ---- Phase C: acc = HsAcc + mem-term; batchnorm; init next accs ----
        {
            int gw = bx * 8 + w;            // one warp per hidden unit j
            int idx = gw * Bz + lane;
            float acc = dHsAcc[idx];
            float sc = eta;
#pragma unroll 4
            for (int tau = t; tau >= 0; tau--) {
                acc += sc * dDotsRaw[tau * Bz + lane]
                          * fmaxf(dHistAcc[(size_t)tau * NH * Bz + idx], 0.f);
                sc *= lam;
            }
            float mu = acc;
#pragma unroll
            for (int o = 16; o > 0; o >>= 1) mu += __shfl_xor_sync(0xffffffffu, mu, o);
            mu *= (1.f / 32.f);
            float dv = acc - mu;
            float vv = dv * dv;
#pragma unroll
            for (int o = 16; o > 0; o >>= 1) vv += __shfl_xor_sync(0xffffffffu, vv, o);
            float sig = sqrtf(vv * (1.f / 32.f));
            dHcur[idx] = fmaxf(g_p[gw] * dv / sig + b_p[gw], 0.f);

            if (t + 1 < T) {                // init next step's accumulators
                float z = dZCt[(size_t)(t + 1) * NH * Bz + idx];
                dHistAcc[(size_t)(t + 1) * NH * Bz + idx] = z;
                dHsAcc[idx] = z;
            } else {
                dOt[idx] = 0.f;             // accumulator for the head GEMM
            }
        }
        gsync();
    }

    // ---- head: dOt += h @ W_ho (pre-relu accumulator) ----
    load_wslice(sm, Who, k0, j0, NH);
    load_aslice_dup<false>(sm, dHcur + (size_t)k0 * Bz);
    __syncthreads();
    slice_gemm_red(sm, dOt, j0);
    gsync();

    // ---- y = relu(relu(dOt) @ W_o): 4 CTAs, each one 64-wide j-tile, full K
    if (bx < 4) {
        int j02 = bx << 6;
        unsigned long long acc[4][2];
#pragma unroll
        for (int i = 0; i < 4; i++) { acc[i][0] = 0ull; acc[i][1] = 0ull; }
        for (int s = 0; s < 8; s++) {
            load_wslice(sm, Wo, s * 128, j02, NOUT);
            load_aslice_dup<true>(sm, dOt + (size_t)s * 128 * Bz);
            __syncthreads();
            gemm_core(sm, acc);
            __syncthreads();
        }
        // combine the two k-halves via smem scratch (As2 area is free now)
        float* scr = &sm->As2[0][0];    // [64j][32b]
        int half = tid >> 7;
        int r = tid & 127;
        int jg = r & 15, bg = r >> 4;
        if (half == 1) {
#pragma unroll
            for (int bb = 0; bb < 4; bb++) {
                float2 u0 = up2(acc[bb][0]);
                float2 u1 = up2(acc[bb][1]);
                scr[(jg * 4 + 0) * 32 + bg * 4 + bb] = u0.x;
                scr[(jg * 4 + 1) * 32 + bg * 4 + bb] = u0.y;
                scr[(jg * 4 + 2) * 32 + bg * 4 + bb] = u1.x;
                scr[(jg * 4 + 3) * 32 + bg * 4 + bb] = u1.y;
            }
        }
        __syncthreads();
        if (half == 0) {
#pragma unroll
            for (int bb = 0; bb < 4; bb++) {
                float2 u0 = up2(acc[bb][0]);
                float2 u1 = up2(acc[bb][1]);
                float v0 = u0.x + scr[(jg * 4 + 0) * 32 + bg * 4 + bb];
                float v1 = u0.y + scr[(jg * 4 + 1) * 32 + bg * 4 + bb];
                float v2 = u1.x + scr[(jg * 4 + 2) * 32 + bg * 4 + bb];
                float v3 = u1.y + scr[(jg * 4 + 3) * 32 + bg * 4 + bb];
                int b = bg * 4 + bb;
                out[(size_t)b * NOUT + j02 + jg * 4 + 0] = fmaxf(v0, 0.f);
                out[(size_t)b * NOUT + j02 + jg * 4 + 1] = fmaxf(v1, 0.f);
                out[(size_t)b * NOUT + j02 + jg * 4 + 2] = fmaxf(v2, 0.f);
                out[(size_t)b * NOUT + j02 + jg * 4 + 3] = fmaxf(v3, 0.f);
            }
        }
    }
}

extern "C" void kernel_launch(void* const* d_in, const int* in_sizes, int n_in,
                              void* d_out, int out_size) {
    (void)in_sizes; (void)n_in; (void)out_size;
    const float* x   = (const float*)d_in[0];
    const float* Wi  = (const float*)d_in[1];
    const float* Wz  = (const float*)d_in[2];
    const float* Wc  = (const float*)d_in[3];
    const float* Wh  = (const float*)d_in[4];
    const float* Who = (const float*)d_in[5];
    const float* Wo  = (const float*)d_in[6];
    const float* lam = (const float*)d_in[7];
    const float* eta = (const float*)d_in[8];
    const float* g   = (const float*)d_in[9];
    const float* b   = (const float*)d_in[10];

    cudaFuncSetAttribute(memnet_rec_kernel,
                         cudaFuncAttributeMaxDynamicSharedMemorySize,
                         (int)sizeof(SmemT));

    k_gemm_s<<<256, 256>>>(x, Wi);
    k_gemm_z<<<256, 256>>>(Wz);
    k_gemm_zc<<<256, 256>>>(Wc);
    memnet_rec_kernel<<<NBLK, NTH, sizeof(SmemT)>>>(Wh, Who, Wo, lam, eta, g, b,
                                                    (float*)d_out);
}

// round 10
// speedup vs baseline: 1.1661x; 1.1661x over previous
#include <cuda_runtime.h>
#include <math.h>

#define T    32
#define Bz   32
#define NIN  512
#define NH   1024
#define NOUT 256
#define NBLK 128      // uniform grid: 8 k-slices x 16 j-tiles
#define NTH  256

// ---------------- persistent state (device globals; no allocation) ----------
__device__ float dS[T * Bz * NH];       // relu(relu(x)@W_i)      [m=(t,b)][k]
__device__ float dZ[T * Bz * NH];       // relu(S@W_z)            [m][k]
__device__ float dZCt[T * NH * Bz];     // Z@W_c transposed       [t][j][b]
__device__ float dHist[T * NH * Bz];    // h_t history (post-relu) [t][j][b]
__device__ float dHcur[NH * Bz];        // post-norm carry        [j][b]
__device__ float dOt[NH * Bz];          // o = relu(h@W_ho)       [j][b]
__device__ float dPartA[8 * NH * Bz];   // split-K partials (phase A / head)
__device__ float dPartB[8 * NH * Bz];   // split-K partials (phase B)
__device__ float dDotsRaw[T * Bz];      // raw dot accumulators [tau][b]
// tree barrier (monotonic counters; zero-init once; graph-replay safe)
__device__ unsigned gLeaf[16 * 32];     // 16 counters, one per 128B line
__device__ unsigned gRoot;
__device__ volatile unsigned gEpoch;

// ---------------- packed f32x2 helpers --------------------------------------
static __device__ __forceinline__ unsigned long long pk2(float v) {
    unsigned long long r;
    asm("mov.b64 %0, {%1, %1};" : "=l"(r) : "f"(v));
    return r;
}
static __device__ __forceinline__ void ffma2(unsigned long long& d,
                                             unsigned long long a,
                                             unsigned long long b) {
    asm("fma.rn.f32x2 %0, %1, %2, %0;" : "+l"(d) : "l"(a), "l"(b));
}
static __device__ __forceinline__ float2 up2(unsigned long long v) {
    float2 f;
    asm("mov.b64 {%0, %1}, %2;" : "=f"(f.x), "=f"(f.y) : "l"(v));
    return f;
}

// ---------------- tree grid barrier (128 CTAs: 16 groups of 8) --------------
__device__ __forceinline__ void gsync() {
    __syncthreads();
    if (threadIdx.x == 0) {
        __threadfence();
        unsigned e = gEpoch;
        if ((atomicAdd(&gLeaf[((unsigned)blockIdx.x >> 3) << 5], 1u) & 7u) == 7u) {
            if ((atomicAdd(&gRoot, 1u) & 15u) == 15u) {
                __threadfence();
                atomicAdd((unsigned*)&gEpoch, 1u);
            }
        }
        while (gEpoch == e) {}
        __threadfence();
    }
    __syncthreads();
}

// ---------------- big GEMM (precompute): C[M,N] = op(A[M,K] @ W[K,N]) -------
template <bool RIN, bool ROUT, bool TST>
__device__ __forceinline__ void gemm_big_dev(const float* __restrict__ A,
                                             const float* __restrict__ W,
                                             float* __restrict__ C,
                                             int M, int N, int K) {
    __shared__ __align__(16) float As[2][16][64];
    __shared__ __align__(16) float Bs[2][16][64];
    int tid = threadIdx.x;
    int tx = tid & 15, ty = tid >> 4;
    int tilesN = N >> 6;
    int m0 = (blockIdx.x / tilesN) << 6;
    int n0 = (blockIdx.x % tilesN) << 6;

    int ra = tid >> 2, ca = (tid & 3) << 2;
    int rb = tid >> 4, cb = (tid & 15) << 2;
    const float* Ap = A + (size_t)(m0 + ra) * K + ca;
    const float* Wp = W + (size_t)rb * N + n0 + cb;

    unsigned long long acc[4][2];
#pragma unroll
    for (int i = 0; i < 4; i++) { acc[i][0] = 0ull; acc[i][1] = 0ull; }

    int nch = K >> 4;
    {
        float4 va = *reinterpret_cast<const float4*>(Ap);
        if (RIN) {
            va.x = fmaxf(va.x, 0.f); va.y = fmaxf(va.y, 0.f);
            va.z = fmaxf(va.z, 0.f); va.w = fmaxf(va.w, 0.f);
        }
        float4 vb = *reinterpret_cast<const float4*>(Wp);
        As[0][ca + 0][ra] = va.x; As[0][ca + 1][ra] = va.y;
        As[0][ca + 2][ra] = va.z; As[0][ca + 3][ra] = va.w;
        *reinterpret_cast<float4*>(&Bs[0][rb][cb]) = vb;
    }
    __syncthreads();

    for (int ch = 0; ch < nch; ch++) {
        int cur = ch & 1;
        float4 va, vb;
        if (ch + 1 < nch) {
            va = *reinterpret_cast<const float4*>(Ap + (ch + 1) * 16);
            vb = *reinterpret_cast<const float4*>(Wp + (size_t)(ch + 1) * 16 * N);
            if (RIN) {
                va.x = fmaxf(va.x, 0.f); va.y = fmaxf(va.y, 0.f);
                va.z = fmaxf(va.z, 0.f); va.w = fmaxf(va.w, 0.f);
            }
        }
#pragma unroll
        for (int k = 0; k < 16; k++) {
            float4 a4 = *reinterpret_cast<float4*>(&As[cur][k][ty * 4]);
            ulonglong2 b2 = *reinterpret_cast<ulonglong2*>(&Bs[cur][k][tx * 4]);
            unsigned long long a0 = pk2(a4.x), a1 = pk2(a4.y);
            unsigned long long a2 = pk2(a4.z), a3 = pk2(a4.w);
            ffma2(acc[0][0], a0, b2.x); ffma2(acc[0][1], a0, b2.y);
            ffma2(acc[1][0], a1, b2.x); ffma2(acc[1][1], a1, b2.y);
            ffma2(acc[2][0], a2, b2.x); ffma2(acc[2][1], a2, b2.y);
            ffma2(acc[3][0], a3, b2.x); ffma2(acc[3][1], a3, b2.y);
        }
        if (ch + 1 < nch) {
            int nxt = cur ^ 1;
            As[nxt][ca + 0][ra] = va.x; As[nxt][ca + 1][ra] = va.y;
            As[nxt][ca + 2][ra] = va.z; As[nxt][ca + 3][ra] = va.w;
            *reinterpret_cast<float4*>(&Bs[nxt][rb][cb]) = vb;
        }
        __syncthreads();
    }
#pragma unroll
    for (int i = 0; i < 4; i++) {
        float2 u0 = up2(acc[i][0]);
        float2 u1 = up2(acc[i][1]);
        float vals[4] = {u0.x, u0.y, u1.x, u1.y};
#pragma unroll
        for (int j = 0; j < 4; j++) {
            float v = vals[j];
            if (ROUT) v = fmaxf(v, 0.f);
            int m = m0 + ty * 4 + i;
            int n = n0 + tx * 4 + j;
            if (TST) {
                C[(((size_t)(m >> 5) * NH) + n) * Bz + (m & 31)] = v;  // [t][n][b]
            } else {
                C[(size_t)m * N + n] = v;
            }
        }
    }
}

__global__ void __launch_bounds__(256) k_gemm_s(const float* __restrict__ x,
                                                const float* __restrict__ Wi) {
    gemm_big_dev<true, true, false>(x, Wi, dS, T * Bz, NH, NIN);
}
__global__ void __launch_bounds__(256) k_gemm_z(const float* __restrict__ Wz) {
    gemm_big_dev<false, true, false>(dS, Wz, dZ, T * Bz, NH, NH);
}
__global__ void __launch_bounds__(256) k_gemm_zc(const float* __restrict__ Wc) {
    gemm_big_dev<false, false, true>(dZ, Wc, dZCt, T * Bz, NH, NH);
}

// ---------------- persistent recurrence kernel ------------------------------
// CTA bx: jt = bx&15 (j0 = jt*64), ks = bx>>4 (k0 = ks*128).
// smem (dynamic, ~72 KB): resident W [128][64] + duplicated A [128][64] + scr.
struct SmemT {
    float Ws[128][64];    // 32 KB  (W[k][j])
    float As2[128][64];   // 32 KB  (A duplicated: As2[k][2b]=As2[k][2b+1]=h[k][b])
    float scr[64][33];    // k-half combine scratch (padded vs bank conflicts)
};

__device__ __forceinline__ void load_wslice(SmemT* sm, const float* __restrict__ W,
                                            int k0, int j0, int ldw) {
    int tid = threadIdx.x;
#pragma unroll
    for (int i = 0; i < 8; i++) {
        int e = (tid + i * NTH) * 4;
        int r = e >> 6, c = e & 63;
        *reinterpret_cast<float4*>(&sm->Ws[r][c]) =
            *reinterpret_cast<const float4*>(W + (size_t)(k0 + r) * ldw + j0 + c);
    }
}

// stage a [128][32] slice from global into duplicated smem As2
template <bool RELU>
__device__ __forceinline__ void load_aslice_dup(SmemT* sm, const float* __restrict__ src) {
    int tid = threadIdx.x;
    const float4* s = reinterpret_cast<const float4*>(src);
#pragma unroll
    for (int i = 0; i < 4; i++) {
        int idx = tid + i * NTH;       // float4 index over 1024
        float4 v = s[idx];
        if (RELU) {
            v.x = fmaxf(v.x, 0.f); v.y = fmaxf(v.y, 0.f);
            v.z = fmaxf(v.z, 0.f); v.w = fmaxf(v.w, 0.f);
        }
        int k = idx >> 3, bq = idx & 7;
        float4 lo = {v.x, v.x, v.y, v.y};
        float4 hi = {v.z, v.z, v.w, v.w};
        *reinterpret_cast<float4*>(&sm->As2[k][bq * 8])     = lo;
        *reinterpret_cast<float4*>(&sm->As2[k][bq * 8 + 4]) = hi;
    }
}

// core GEMM over resident tiles: 4b x 4j per thread, 2-way k-split by tid>>7
__device__ __forceinline__ void gemm_core(SmemT* sm, unsigned long long acc[4][2]) {
    int tid = threadIdx.x;
    int half = tid >> 7;
    int r = tid & 127;
    int jg = r & 15;      // j group of 4
    int bg = r >> 4;      // b group of 4 (0..7)
    const float* wsr = &sm->Ws[half << 6][jg * 4];
    const float* asr = &sm->As2[half << 6][bg * 8];
#pragma unroll 8
    for (int k = 0; k < 64; k++) {
        ulonglong2 w2  = *reinterpret_cast<const ulonglong2*>(wsr);
        ulonglong2 a01 = *reinterpret_cast<const ulonglong2*>(asr);
        ulonglong2 a23 = *reinterpret_cast<const ulonglong2*>(asr + 4);
        ffma2(acc[0][0], a01.x, w2.x); ffma2(acc[0][1], a01.x, w2.y);
        ffma2(acc[1][0], a01.y, w2.x); ffma2(acc[1][1], a01.y, w2.y);
        ffma2(acc[2][0], a23.x, w2.x); ffma2(acc[2][1], a23.x, w2.y);
        ffma2(acc[3][0], a23.y, w2.x); ffma2(acc[3][1], a23.y, w2.y);
        wsr += 64; asr += 64;
    }
}

// GEMM -> combine k-halves in smem -> STG.128 into partial slice [j][b]
__device__ __forceinline__ void slice_gemm_stg(SmemT* sm, float* __restrict__ pslice,
                                               int j0) {
    unsigned long long acc[4][2];
#pragma unroll
    for (int i = 0; i < 4; i++) { acc[i][0] = 0ull; acc[i][1] = 0ull; }
    gemm_core(sm, acc);
    int tid = threadIdx.x;
    int half = tid >> 7;
    int r = tid & 127;
    int jg = r & 15, bg = r >> 4;
    if (half == 1) {
#pragma unroll
        for (int bb = 0; bb < 4; bb++) {
            float2 u0 = up2(acc[bb][0]);
            float2 u1 = up2(acc[bb][1]);
            sm->scr[jg * 4 + 0][bg * 4 + bb] = u0.x;
            sm->scr[jg * 4 + 1][bg * 4 + bb] = u0.y;
            sm->scr[jg * 4 + 2][bg * 4 + bb] = u1.x;
            sm->scr[jg * 4 + 3][bg * 4 + bb] = u1.y;
        }
    }
    __syncthreads();
    if (half == 0) {
        float v[4][4];   // v[q][bb] = out[j0+jg*4+q][bg*4+bb]
#pragma unroll
        for (int bb = 0; bb < 4; bb++) {
            float2 u0 = up2(acc[bb][0]);
            float2 u1 = up2(acc[bb][1]);
            v[0][bb] = u0.x + sm->scr[jg * 4 + 0][bg * 4 + bb];
            v[1][bb] = u0.y + sm->scr[jg * 4 + 1][bg * 4 + bb];
            v[2][bb] = u1.x + sm->scr[jg * 4 + 2][bg * 4 + bb];
            v[3][bb] = u1.y + sm->scr[jg * 4 + 3][bg * 4 + bb];
        }
#pragma unroll
        for (int q = 0; q < 4; q++) {
            float4 o = {v[q][0], v[q][1], v[q][2], v[q][3]};
            *reinterpret_cast<float4*>(
                &pslice[(size_t)(j0 + jg * 4 + q) * Bz + bg * 4]) = o;
        }
    }
}

__global__ void __launch_bounds__(NTH, 1)
memnet_rec_kernel(const float* __restrict__ Wh,  const float* __restrict__ Who,
                  const float* __restrict__ Wo,  const float* __restrict__ lam_p,
                  const float* __restrict__ eta_p, const float* __restrict__ g_p,
                  const float* __restrict__ b_p, float* __restrict__ out) {
    extern __shared__ __align__(16) char smembuf[];
    SmemT* sm = reinterpret_cast<SmemT*>(smembuf);
    int bx   = blockIdx.x;
    int tid  = threadIdx.x;
    int lane = tid & 31;
    int w    = tid >> 5;
    int jt = bx & 15, ks = bx >> 4;
    int j0 = jt << 6, k0 = ks << 7;

    load_wslice(sm, Wh, k0, j0, NH);
    if (bx == 0) {                      // zero dot accumulators for t=0
        float4 z = {0.f, 0.f, 0.f, 0.f};
        reinterpret_cast<float4*>(dDotsRaw)[tid] = z;
    }
    gsync();

    const float lam = lam_p[0];
    const float eta = eta_p[0];

    for (int t = 0; t < T; t++) {
        const float* zc = dZCt + (size_t)t * NH * Bz;
        float* Ht = dHist + (size_t)t * NH * Bz;

        // ---- Phase A: partials of h_prev @ W_h; zero dDotsRaw (t>0) --------
        if (t > 0) {
            load_aslice_dup<false>(sm, dHcur + (size_t)k0 * Bz);
            if (bx == 0) {
                float4 z = {0.f, 0.f, 0.f, 0.f};
                reinterpret_cast<float4*>(dDotsRaw)[tid] = z;
            }
            __syncthreads();
            slice_gemm_stg(sm, dPartA + (size_t)ks * NH * Bz, j0);
            gsync();
        }

        // ---- Phase B: build Ht slice (dup) in smem; dots; GEMM Ht @ W_h ----
        {
            // build Ht slice = relu(zc + sum partials) into As2 (+ global by jt==0)
            const float4* zc4 = reinterpret_cast<const float4*>(zc + (size_t)k0 * Bz);
#pragma unroll
            for (int i = 0; i < 4; i++) {
                int idx = tid + i * NTH;
                float4 v = zc4[idx];
                if (t > 0) {
#pragma unroll
                    for (int s = 0; s < 8; s++) {
                        float4 p = reinterpret_cast<const float4*>(
                            dPartA + (size_t)s * NH * Bz + (size_t)k0 * Bz)[idx];
                        v.x += p.x; v.y += p.y; v.z += p.z; v.w += p.w;
                    }
                }
                v.x = fmaxf(v.x, 0.f); v.y = fmaxf(v.y, 0.f);
                v.z = fmaxf(v.z, 0.f); v.w = fmaxf(v.w, 0.f);
                int k = idx >> 3, bq = idx & 7;
                float4 lo = {v.x, v.x, v.y, v.y};
                float4 hi = {v.z, v.z, v.w, v.w};
                *reinterpret_cast<float4*>(&sm->As2[k][bq * 8])     = lo;
                *reinterpret_cast<float4*>(&sm->As2[k][bq * 8 + 4]) = hi;
                if (jt == 0)
                    reinterpret_cast<float4*>(Ht + (size_t)k0 * Bz)[idx] = v;
            }
            __syncthreads();

            // dots: this CTA handles tau = jt, jt+16 (<= t) over its k-slice
            for (int tau = jt; tau <= t; tau += 16) {
                float a = 0.f;
                int kb = w << 4;
                if (tau == t) {
#pragma unroll
                    for (int kk = 0; kk < 16; kk++) {
                        float xv = sm->As2[kb + kk][lane * 2];
                        a += xv * xv;
                    }
                } else {
                    const float* Hs = dHist + (size_t)tau * NH * Bz + (size_t)k0 * Bz;
#pragma unroll
                    for (int kk = 0; kk < 16; kk++)
                        a += sm->As2[kb + kk][lane * 2] * Hs[(kb + kk) * Bz + lane];
                }
                atomicAdd(&dDotsRaw[tau * Bz + lane], a);
            }

            slice_gemm_stg(sm, dPartB + (size_t)ks * NH * Bz, j0);
        }
        gsync();

        // ---- Phase C: hs = HtWh + zc + mem-term; batchnorm over b ----------
        {
            int gw = bx * 8 + w;            // one warp per hidden unit j
            int idx = gw * Bz + lane;
            float acc = zc[idx];
#pragma unroll
            for (int s = 0; s < 8; s++) acc += dPartB[(size_t)s * NH * Bz + idx];
            float sc = eta;
#pragma unroll 8
            for (int tau = t; tau >= 0; tau--) {
                acc += sc * dDotsRaw[tau * Bz + lane]
                          * dHist[(size_t)tau * NH * Bz + idx];
                sc *= lam;
            }
            float mu = acc;
#pragma unroll
            for (int o = 16; o > 0; o >>= 1) mu += __shfl_xor_sync(0xffffffffu, mu, o);
            mu *= (1.f / 32.f);
            float dv = acc - mu;
            float vv = dv * dv;
#pragma unroll
            for (int o = 16; o > 0; o >>= 1) vv += __shfl_xor_sync(0xffffffffu, vv, o);
            float rs = rsqrtf(vv * (1.f / 32.f));
            dHcur[idx] = fmaxf(g_p[gw] * dv * rs + b_p[gw], 0.f);
        }
        gsync();
    }

    // ---- head: o = relu(h @ W_ho) ----
    load_wslice(sm, Who, k0, j0, NH);
    load_aslice_dup<false>(sm, dHcur + (size_t)k0 * Bz);
    __syncthreads();
    slice_gemm_stg(sm, dPartA + (size_t)ks * NH * Bz, j0);
    gsync();
    for (int i = (bx * NTH + tid) * 4; i < NH * Bz; i += NBLK * NTH * 4) {
        float4 v = *reinterpret_cast<const float4*>(dPartA + i);
#pragma unroll
        for (int s = 1; s < 8; s++) {
            float4 p = *reinterpret_cast<const float4*>(dPartA + (size_t)s * NH * Bz + i);
            v.x += p.x; v.y += p.y; v.z += p.z; v.w += p.w;
        }
        v.x = fmaxf(v.x, 0.f); v.y = fmaxf(v.y, 0.f);
        v.z = fmaxf(v.z, 0.f); v.w = fmaxf(v.w, 0.f);
        *reinterpret_cast<float4*>(dOt + i) = v;
    }
    gsync();

    // ---- y = relu(o @ W_o) ----  32 jobs: 4 jt x 8 ks
    if (bx < 32) {
        int jt2 = bx & 3, ks2 = bx >> 2;
        int j02 = jt2 << 6, k02 = ks2 << 7;
        load_wslice(sm, Wo, k02, j02, NOUT);
        load_aslice_dup<false>(sm, dOt + (size_t)k02 * Bz);
        __syncthreads();
        slice_gemm_stg(sm, dPartA + (size_t)ks2 * NOUT * Bz, j02);
    }
    gsync();
    for (int i = bx * NTH + tid; i < NOUT * Bz; i += NBLK * NTH) {
        float v = 0.f;
#pragma unroll
        for (int s = 0; s < 8; s++) v += dPartA[(size_t)s * NOUT * Bz + i];
        int n = i >> 5, b = i & 31;
        out[(size_t)b * NOUT + n] = fmaxf(v, 0.f);
    }
}

extern "C" void kernel_launch(void* const* d_in, const int* in_sizes, int n_in,
                              void* d_out, int out_size) {
    (void)in_sizes; (void)n_in; (void)out_size;
    const float* x   = (const float*)d_in[0];
    const float* Wi  = (const float*)d_in[1];
    const float* Wz  = (const float*)d_in[2];
    const float* Wc  = (const float*)d_in[3];
    const float* Wh  = (const float*)d_in[4];
    const float* Who = (const float*)d_in[5];
    const float* Wo  = (const float*)d_in[6];
    const float* lam = (const float*)d_in[7];
    const float* eta = (const float*)d_in[8];
    const float* g   = (const float*)d_in[9];
    const float* b   = (const float*)d_in[10];

    cudaFuncSetAttribute(memnet_rec_kernel,
                         cudaFuncAttributeMaxDynamicSharedMemorySize,
                         (int)sizeof(SmemT));

    k_gemm_s<<<256, 256>>>(x, Wi);
    k_gemm_z<<<256, 256>>>(Wz);
    k_gemm_zc<<<256, 256>>>(Wc);
    memnet_rec_kernel<<<NBLK, NTH, sizeof(SmemT)>>>(Wh, Who, Wo, lam, eta, g, b,
                                                    (float*)d_out);
}

// round 15
// speedup vs baseline: 1.1805x; 1.0123x over previous
#include <cuda_runtime.h>
#include <math.h>

#define T    32
#define Bz   32
#define NIN  512
#define NH   1024
#define NOUT 256
#define NBLK 128      // uniform grid: 8 k-slices x 16 j-tiles
#define NTH  512

// ---------------- persistent state (device globals; no allocation) ----------
__device__ float dS[T * Bz * NH];       // relu(relu(x)@W_i)      [m=(t,b)][k]
__device__ float dZ[T * Bz * NH];       // relu(S@W_z)            [m][k]
__device__ float dZCt[T * NH * Bz];     // Z@W_c transposed       [t][j][b]
__device__ float dHist[T * NH * Bz];    // h_t history (post-relu) [t][j][b]
__device__ float dHcur[NH * Bz];        // post-norm carry        [j][b]
__device__ float dOt[NH * Bz];          // o = relu(h@W_ho)       [j][b]
__device__ float dPartA[8 * NH * Bz];   // split-K partials (phase A / head)
__device__ float dPartB[8 * NH * Bz];   // split-K partials (phase B)
__device__ float dDotsRaw[T * Bz];      // raw dot accumulators [tau][b]
// tree barrier (monotonic counters; zero-init once; graph-replay safe)
__device__ unsigned gLeaf[16 * 32];     // 16 counters, one per 128B line
__device__ unsigned gRoot;
__device__ volatile unsigned gEpoch;

// ---------------- packed f32x2 helpers --------------------------------------
static __device__ __forceinline__ unsigned long long pk2(float v) {
    unsigned long long r;
    asm("mov.b64 %0, {%1, %1};" : "=l"(r) : "f"(v));
    return r;
}
static __device__ __forceinline__ void ffma2(unsigned long long& d,
                                             unsigned long long a,
                                             unsigned long long b) {
    asm("fma.rn.f32x2 %0, %1, %2, %0;" : "+l"(d) : "l"(a), "l"(b));
}
static __device__ __forceinline__ float2 up2(unsigned long long v) {
    float2 f;
    asm("mov.b64 {%0, %1}, %2;" : "=f"(f.x), "=f"(f.y) : "l"(v));
    return f;
}

// ---------------- tree grid barrier (128 CTAs: 16 groups of 8) --------------
__device__ __forceinline__ void gsync() {
    __syncthreads();
    if (threadIdx.x == 0) {
        __threadfence();
        unsigned e = gEpoch;
        if ((atomicAdd(&gLeaf[((unsigned)blockIdx.x >> 3) << 5], 1u) & 7u) == 7u) {
            if ((atomicAdd(&gRoot, 1u) & 15u) == 15u) {
                __threadfence();
                atomicAdd((unsigned*)&gEpoch, 1u);
            }
        }
        while (gEpoch == e) {}
        __threadfence();
    }
    __syncthreads();
}

// ---------------- big GEMM (precompute): C[M,N] = op(A[M,K] @ W[K,N]) -------
template <bool RIN, bool ROUT, bool TST>
__device__ __forceinline__ void gemm_big_dev(const float* __restrict__ A,
                                             const float* __restrict__ W,
                                             float* __restrict__ C,
                                             int M, int N, int K) {
    __shared__ __align__(16) float As[2][16][64];
    __shared__ __align__(16) float Bs[2][16][64];
    int tid = threadIdx.x;
    int tx = tid & 15, ty = tid >> 4;
    int tilesN = N >> 6;
    int m0 = (blockIdx.x / tilesN) << 6;
    int n0 = (blockIdx.x % tilesN) << 6;

    int ra = tid >> 2, ca = (tid & 3) << 2;
    int rb = tid >> 4, cb = (tid & 15) << 2;
    const float* Ap = A + (size_t)(m0 + ra) * K + ca;
    const float* Wp = W + (size_t)rb * N + n0 + cb;

    unsigned long long acc[4][2];
#pragma unroll
    for (int i = 0; i < 4; i++) { acc[i][0] = 0ull; acc[i][1] = 0ull; }

    int nch = K >> 4;
    {
        float4 va = *reinterpret_cast<const float4*>(Ap);
        if (RIN) {
            va.x = fmaxf(va.x, 0.f); va.y = fmaxf(va.y, 0.f);
            va.z = fmaxf(va.z, 0.f); va.w = fmaxf(va.w, 0.f);
        }
        float4 vb = *reinterpret_cast<const float4*>(Wp);
        As[0][ca + 0][ra] = va.x; As[0][ca + 1][ra] = va.y;
        As[0][ca + 2][ra] = va.z; As[0][ca + 3][ra] = va.w;
        *reinterpret_cast<float4*>(&Bs[0][rb][cb]) = vb;
    }
    __syncthreads();

    for (int ch = 0; ch < nch; ch++) {
        int cur = ch & 1;
        float4 va, vb;
        if (ch + 1 < nch) {
            va = *reinterpret_cast<const float4*>(Ap + (ch + 1) * 16);
            vb = *reinterpret_cast<const float4*>(Wp + (size_t)(ch + 1) * 16 * N);
            if (RIN) {
                va.x = fmaxf(va.x, 0.f); va.y = fmaxf(va.y, 0.f);
                va.z = fmaxf(va.z, 0.f); va.w = fmaxf(va.w, 0.f);
            }
        }
#pragma unroll
        for (int k = 0; k < 16; k++) {
            float4 a4 = *reinterpret_cast<float4*>(&As[cur][k][ty * 4]);
            ulonglong2 b2 = *reinterpret_cast<ulonglong2*>(&Bs[cur][k][tx * 4]);
            unsigned long long a0 = pk2(a4.x), a1 = pk2(a4.y);
            unsigned long long a2 = pk2(a4.z), a3 = pk2(a4.w);
            ffma2(acc[0][0], a0, b2.x); ffma2(acc[0][1], a0, b2.y);
            ffma2(acc[1][0], a1, b2.x); ffma2(acc[1][1], a1, b2.y);
            ffma2(acc[2][0], a2, b2.x); ffma2(acc[2][1], a2, b2.y);
            ffma2(acc[3][0], a3, b2.x); ffma2(acc[3][1], a3, b2.y);
        }
        if (ch + 1 < nch) {
            int nxt = cur ^ 1;
            As[nxt][ca + 0][ra] = va.x; As[nxt][ca + 1][ra] = va.y;
            As[nxt][ca + 2][ra] = va.z; As[nxt][ca + 3][ra] = va.w;
            *reinterpret_cast<float4*>(&Bs[nxt][rb][cb]) = vb;
        }
        __syncthreads();
    }
#pragma unroll
    for (int i = 0; i < 4; i++) {
        float2 u0 = up2(acc[i][0]);
        float2 u1 = up2(acc[i][1]);
        float vals[4] = {u0.x, u0.y, u1.x, u1.y};
#pragma unroll
        for (int j = 0; j < 4; j++) {
            float v = vals[j];
            if (ROUT) v = fmaxf(v, 0.f);
            int m = m0 + ty * 4 + i;
            int n = n0 + tx * 4 + j;
            if (TST) {
                C[(((size_t)(m >> 5) * NH) + n) * Bz + (m & 31)] = v;  // [t][n][b]
            } else {
                C[(size_t)m * N + n] = v;
            }
        }
    }
}

__global__ void __launch_bounds__(256) k_gemm_s(const float* __restrict__ x,
                                                const float* __restrict__ Wi) {
    gemm_big_dev<true, true, false>(x, Wi, dS, T * Bz, NH, NIN);
}
__global__ void __launch_bounds__(256) k_gemm_z(const float* __restrict__ Wz) {
    gemm_big_dev<false, true, false>(dS, Wz, dZ, T * Bz, NH, NH);
}
__global__ void __launch_bounds__(256) k_gemm_zc(const float* __restrict__ Wc) {
    gemm_big_dev<false, false, true>(dZ, Wc, dZCt, T * Bz, NH, NH);
}

// ---------------- persistent recurrence kernel (512 threads) ----------------
// CTA bx: jt = bx&15 (j0 = jt*64), ks = bx>>4 (k0 = ks*128).
// smem (~101 KB): resident W [128][64] + duplicated A [128][64] + 4 scratch.
// scr rows padded to 36 floats (144 B = 9*16) so float4 reads stay aligned.
struct SmemT {
    float Ws[128][64];      // 32 KB  (W[k][j])
    float As2[128][64];     // 32 KB  (A duplicated: As2[k][2b]=As2[k][2b+1])
    float scr[4][64][36];   // per-quarter combine scratch (16B-aligned rows)
};

__device__ __forceinline__ void load_wslice(SmemT* sm, const float* __restrict__ W,
                                            int k0, int j0, int ldw) {
    int tid = threadIdx.x;
#pragma unroll
    for (int i = 0; i < 4; i++) {
        int e = (tid + i * NTH) * 4;
        int r = e >> 6, c = e & 63;
        *reinterpret_cast<float4*>(&sm->Ws[r][c]) =
            *reinterpret_cast<const float4*>(W + (size_t)(k0 + r) * ldw + j0 + c);
    }
}

// stage a [128][32] slice from global into duplicated smem As2
template <bool RELU>
__device__ __forceinline__ void load_aslice_dup(SmemT* sm, const float* __restrict__ src) {
    int tid = threadIdx.x;
    const float4* s = reinterpret_cast<const float4*>(src);
#pragma unroll
    for (int i = 0; i < 2; i++) {
        int idx = tid + i * NTH;       // float4 index over 1024
        float4 v = s[idx];
        if (RELU) {
            v.x = fmaxf(v.x, 0.f); v.y = fmaxf(v.y, 0.f);
            v.z = fmaxf(v.z, 0.f); v.w = fmaxf(v.w, 0.f);
        }
        int k = idx >> 3, bq = idx & 7;
        float4 lo = {v.x, v.x, v.y, v.y};
        float4 hi = {v.z, v.z, v.w, v.w};
        *reinterpret_cast<float4*>(&sm->As2[k][bq * 8])     = lo;
        *reinterpret_cast<float4*>(&sm->As2[k][bq * 8 + 4]) = hi;
    }
}

// core GEMM: 4b x 4j per thread, 4-way k-split (quarter = tid>>7, 32 k each)
__device__ __forceinline__ void gemm_core(SmemT* sm, unsigned long long acc[4][2]) {
    int tid = threadIdx.x;
    int q = tid >> 7;
    int r = tid & 127;
    int jg = r & 15;      // j group of 4
    int bg = r >> 4;      // b group of 4 (0..7)
    const float* wsr = &sm->Ws[q << 5][jg * 4];
    const float* asr = &sm->As2[q << 5][bg * 8];
#pragma unroll 8
    for (int k = 0; k < 32; k++) {
        ulonglong2 w2  = *reinterpret_cast<const ulonglong2*>(wsr);
        ulonglong2 a01 = *reinterpret_cast<const ulonglong2*>(asr);
        ulonglong2 a23 = *reinterpret_cast<const ulonglong2*>(asr + 4);
        ffma2(acc[0][0], a01.x, w2.x); ffma2(acc[0][1], a01.x, w2.y);
        ffma2(acc[1][0], a01.y, w2.x); ffma2(acc[1][1], a01.y, w2.y);
        ffma2(acc[2][0], a23.x, w2.x); ffma2(acc[2][1], a23.x, w2.y);
        ffma2(acc[3][0], a23.y, w2.x); ffma2(acc[3][1], a23.y, w2.y);
        wsr += 64; asr += 64;
    }
}

// GEMM -> combine 4 k-quarters through smem -> STG.128 into partial slice
__device__ __forceinline__ void slice_gemm_stg(SmemT* sm, float* __restrict__ pslice,
                                               int j0) {
    unsigned long long acc[4][2];
#pragma unroll
    for (int i = 0; i < 4; i++) { acc[i][0] = 0ull; acc[i][1] = 0ull; }
    gemm_core(sm, acc);
    int tid = threadIdx.x;
    int q = tid >> 7;
    int r = tid & 127;
    int jg = r & 15, bg = r >> 4;
#pragma unroll
    for (int bb = 0; bb < 4; bb++) {
        float2 u0 = up2(acc[bb][0]);
        float2 u1 = up2(acc[bb][1]);
        sm->scr[q][jg * 4 + 0][bg * 4 + bb] = u0.x;
        sm->scr[q][jg * 4 + 1][bg * 4 + bb] = u0.y;
        sm->scr[q][jg * 4 + 2][bg * 4 + bb] = u1.x;
        sm->scr[q][jg * 4 + 3][bg * 4 + bb] = u1.y;
    }
    __syncthreads();
    // 512 threads: thread -> (j = tid>>3, bq = (tid&7)*4); rows 16B-aligned
    int j = tid >> 3, bq = (tid & 7) << 2;
    float4 v0 = *reinterpret_cast<const float4*>(&sm->scr[0][j][bq]);
    float4 v1 = *reinterpret_cast<const float4*>(&sm->scr[1][j][bq]);
    float4 v2 = *reinterpret_cast<const float4*>(&sm->scr[2][j][bq]);
    float4 v3 = *reinterpret_cast<const float4*>(&sm->scr[3][j][bq]);
    float4 o = {v0.x + v1.x + v2.x + v3.x,
                v0.y + v1.y + v2.y + v3.y,
                v0.z + v1.z + v2.z + v3.z,
                v0.w + v1.w + v2.w + v3.w};
    *reinterpret_cast<float4*>(&pslice[(size_t)(j0 + j) * Bz + bq]) = o;
}

__global__ void __launch_bounds__(NTH, 1)
memnet_rec_kernel(const float* __restrict__ Wh,  const float* __restrict__ Who,
                  const float* __restrict__ Wo,  const float* __restrict__ lam_p,
                  const float* __restrict__ eta_p, const float* __restrict__ g_p,
                  const float* __restrict__ b_p, float* __restrict__ out) {
    extern __shared__ __align__(16) char smembuf[];
    SmemT* sm = reinterpret_cast<SmemT*>(smembuf);
    int bx   = blockIdx.x;
    int tid  = threadIdx.x;
    int lane = tid & 31;
    int w    = tid >> 5;
    int jt = bx & 15, ks = bx >> 4;
    int j0 = jt << 6, k0 = ks << 7;

    load_wslice(sm, Wh, k0, j0, NH);
    if (bx == 0 && tid < 256) {         // zero dot accumulators for t=0
        float4 z = {0.f, 0.f, 0.f, 0.f};
        reinterpret_cast<float4*>(dDotsRaw)[tid] = z;
    }
    gsync();

    const float lam = lam_p[0];
    const float eta = eta_p[0];
    const float lam2 = lam * lam;

    for (int t = 0; t < T; t++) {
        const float* zc = dZCt + (size_t)t * NH * Bz;
        float* Ht = dHist + (size_t)t * NH * Bz;

        // ---- Phase A: partials of h_prev @ W_h; zero dDotsRaw (t>0) --------
        if (t > 0) {
            load_aslice_dup<false>(sm, dHcur + (size_t)k0 * Bz);
            if (bx == 0 && tid < 256) {
                float4 z = {0.f, 0.f, 0.f, 0.f};
                reinterpret_cast<float4*>(dDotsRaw)[tid] = z;
            }
            __syncthreads();
            slice_gemm_stg(sm, dPartA + (size_t)ks * NH * Bz, j0);
            gsync();
        }

        // ---- Phase B: build Ht slice (dup) in smem; dots; GEMM Ht @ W_h ----
        {
            // build Ht slice = relu(zc + sum partials) into As2 (+ global by jt==0)
            const float4* zc4 = reinterpret_cast<const float4*>(zc + (size_t)k0 * Bz);
#pragma unroll
            for (int i = 0; i < 2; i++) {
                int idx = tid + i * NTH;
                float4 v = zc4[idx];
                if (t > 0) {
#pragma unroll
                    for (int s = 0; s < 8; s++) {
                        float4 p = reinterpret_cast<const float4*>(
                            dPartA + (size_t)s * NH * Bz + (size_t)k0 * Bz)[idx];
                        v.x += p.x; v.y += p.y; v.z += p.z; v.w += p.w;
                    }
                }
                v.x = fmaxf(v.x, 0.f); v.y = fmaxf(v.y, 0.f);
                v.z = fmaxf(v.z, 0.f); v.w = fmaxf(v.w, 0.f);
                int k = idx >> 3, bq = idx & 7;
                float4 lo = {v.x, v.x, v.y, v.y};
                float4 hi = {v.z, v.z, v.w, v.w};
                *reinterpret_cast<float4*>(&sm->As2[k][bq * 8])     = lo;
                *reinterpret_cast<float4*>(&sm->As2[k][bq * 8 + 4]) = hi;
                if (jt == 0)
                    reinterpret_cast<float4*>(Ht + (size_t)k0 * Bz)[idx] = v;
            }
            __syncthreads();

            // dots: this CTA handles tau = jt, jt+16 (<= t); 16 warps x 8 k
            for (int tau = jt; tau <= t; tau += 16) {
                float a = 0.f;
                int kb = w << 3;
                if (tau == t) {
#pragma unroll
                    for (int kk = 0; kk < 8; kk++) {
                        float xv = sm->As2[kb + kk][lane * 2];
                        a += xv * xv;
                    }
                } else {
                    const float* Hs = dHist + (size_t)tau * NH * Bz + (size_t)k0 * Bz;
#pragma unroll
                    for (int kk = 0; kk < 8; kk++)
                        a += sm->As2[kb + kk][lane * 2] * Hs[(kb + kk) * Bz + lane];
                }
                atomicAdd(&dDotsRaw[tau * Bz + lane], a);
            }

            slice_gemm_stg(sm, dPartB + (size_t)ks * NH * Bz, j0);
        }
        gsync();

        // ---- Phase C: hs = HtWh + zc + mem-term; batchnorm; tau split ------
        {
            int w2 = w >> 1, half = w & 1;  // warp pair per hidden unit
            int gw = bx * 8 + w2;
            int idx = gw * Bz + lane;
            float acc = 0.f;
            if (half == 0) {
                acc = zc[idx];
#pragma unroll
                for (int s = 0; s < 8; s++) acc += dPartB[(size_t)s * NH * Bz + idx];
            }
            float sc = half ? eta * lam : eta;
#pragma unroll 4
            for (int tau = t - half; tau >= 0; tau -= 2) {
                acc += sc * dDotsRaw[tau * Bz + lane]
                          * dHist[(size_t)tau * NH * Bz + idx];
                sc *= lam2;
            }
            __syncthreads();
            float* c2 = &sm->scr[0][0][0];
            if (half == 1) c2[w2 * 32 + lane] = acc;
            __syncthreads();
            if (half == 0) {
                acc += c2[w2 * 32 + lane];
                float mu = acc;
#pragma unroll
                for (int o = 16; o > 0; o >>= 1) mu += __shfl_xor_sync(0xffffffffu, mu, o);
                mu *= (1.f / 32.f);
                float dv = acc - mu;
                float vv = dv * dv;
#pragma unroll
                for (int o = 16; o > 0; o >>= 1) vv += __shfl_xor_sync(0xffffffffu, vv, o);
                float rs = rsqrtf(vv * (1.f / 32.f));
                dHcur[idx] = fmaxf(g_p[gw] * dv * rs + b_p[gw], 0.f);
            }
        }
        gsync();
    }

    // ---- head: o = relu(h @ W_ho) ----
    load_wslice(sm, Who, k0, j0, NH);
    load_aslice_dup<false>(sm, dHcur + (size_t)k0 * Bz);
    __syncthreads();
    slice_gemm_stg(sm, dPartA + (size_t)ks * NH * Bz, j0);
    gsync();
    for (int i = (bx * NTH + tid) * 4; i < NH * Bz; i += NBLK * NTH * 4) {
        float4 v = *reinterpret_cast<const float4*>(dPartA + i);
#pragma unroll
        for (int s = 1; s < 8; s++) {
            float4 p = *reinterpret_cast<const float4*>(dPartA + (size_t)s * NH * Bz + i);
            v.x += p.x; v.y += p.y; v.z += p.z; v.w += p.w;
        }
        v.x = fmaxf(v.x, 0.f); v.y = fmaxf(v.y, 0.f);
        v.z = fmaxf(v.z, 0.f); v.w = fmaxf(v.w, 0.f);
        *reinterpret_cast<float4*>(dOt + i) = v;
    }
    gsync();

    // ---- y = relu(o @ W_o) ----  32 jobs: 4 jt x 8 ks
    if (bx < 32) {
        int jt2 = bx & 3, ks2 = bx >> 2;
        int j02 = jt2 << 6, k02 = ks2 << 7;
        load_wslice(sm, Wo, k02, j02, NOUT);
        load_aslice_dup<false>(sm, dOt + (size_t)k02 * Bz);
        __syncthreads();
        slice_gemm_stg(sm, dPartA + (size_t)ks2 * NOUT * Bz, j02);
    }
    gsync();
    for (int i = bx * NTH + tid; i < NOUT * Bz; i += NBLK * NTH) {
        float v = 0.f;
#pragma unroll
        for (int s = 0; s < 8; s++) v += dPartA[(size_t)s * NOUT * Bz + i];
        int n = i >> 5, b = i & 31;
        out[(size_t)b * NOUT + n] = fmaxf(v, 0.f);
    }
}

extern "C" void kernel_launch(void* const* d_in, const int* in_sizes, int n_in,
                              void* d_out, int out_size) {
    (void)in_sizes; (void)n_in; (void)out_size;
    const float* x   = (const float*)d_in[0];
    const float* Wi  = (const float*)d_in[1];
    const float* Wz  = (const float*)d_in[2];
    const float* Wc  = (const float*)d_in[3];
    const float* Wh  = (const float*)d_in[4];
    const float* Who = (const float*)d_in[5];
    const float* Wo  = (const float*)d_in[6];
    const float* lam = (const float*)d_in[7];
    const float* eta = (const float*)d_in[8];
    const float* g   = (const float*)d_in[9];
    const float* b   = (const float*)d_in[10];

    cudaFuncSetAttribute(memnet_rec_kernel,
                         cudaFuncAttributeMaxDynamicSharedMemorySize,
                         (int)sizeof(SmemT));

    k_gemm_s<<<256, 256>>>(x, Wi);
    k_gemm_z<<<256, 256>>>(Wz);
    k_gemm_zc<<<256, 256>>>(Wc);
    memnet_rec_kernel<<<NBLK, NTH, sizeof(SmemT)>>>(Wh, Who, Wo, lam, eta, g, b,
                                                    (float*)d_out);
}

// round 16
// speedup vs baseline: 1.1920x; 1.0098x over previous
#include <cuda_runtime.h>
#include <math.h>

#define T    32
#define Bz   32
#define NIN  512
#define NH   1024
#define NOUT 256
#define NBLK 128      // CTA bx owns output columns [8bx, 8bx+8)
#define NTH  512

// ---------------- persistent state (device globals; no allocation) ----------
__device__ float dS[T * Bz * NH];       // relu(relu(x)@W_i)      [m=(t,b)][k]
__device__ float dZ[T * Bz * NH];       // relu(S@W_z)            [m][k]
__device__ float dZCt[T * NH * Bz];     // Z@W_c transposed       [t][j][b]
__device__ float dHist[T * NH * Bz];    // h_t history (post-relu) [t][j][b]
__device__ float dHcur[NH * Bz];        // post-norm carry        [j][b]
__device__ float dOt[NH * Bz];          // o = relu(h@W_ho)       [j][b]
__device__ float dDot2[2 * T * Bz];     // parity-buffered dot accumulators
// tree barrier (monotonic counters; zero-init once; graph-replay safe)
__device__ unsigned gLeaf[16 * 32];     // 16 counters, one per 128B line
__device__ unsigned gRoot;
__device__ volatile unsigned gEpoch;

// ---------------- packed f32x2 helpers --------------------------------------
static __device__ __forceinline__ unsigned long long pk2(float v) {
    unsigned long long r;
    asm("mov.b64 %0, {%1, %1};" : "=l"(r) : "f"(v));
    return r;
}
static __device__ __forceinline__ void ffma2(unsigned long long& d,
                                             unsigned long long a,
                                             unsigned long long b) {
    asm("fma.rn.f32x2 %0, %1, %2, %0;" : "+l"(d) : "l"(a), "l"(b));
}
static __device__ __forceinline__ float2 up2(unsigned long long v) {
    float2 f;
    asm("mov.b64 {%0, %1}, %2;" : "=f"(f.x), "=f"(f.y) : "l"(v));
    return f;
}

// ---------------- tree grid barrier (128 CTAs: 16 groups of 8) --------------
__device__ __forceinline__ void gsync() {
    __syncthreads();
    if (threadIdx.x == 0) {
        __threadfence();
        unsigned e = gEpoch;
        if ((atomicAdd(&gLeaf[((unsigned)blockIdx.x >> 3) << 5], 1u) & 7u) == 7u) {
            if ((atomicAdd(&gRoot, 1u) & 15u) == 15u) {
                __threadfence();
                atomicAdd((unsigned*)&gEpoch, 1u);
            }
        }
        while (gEpoch == e) {}
        __threadfence();
    }
    __syncthreads();
}

// ---------------- big GEMM (precompute): C[M,N] = op(A[M,K] @ W[K,N]) -------
template <bool RIN, bool ROUT, bool TST>
__device__ __forceinline__ void gemm_big_dev(const float* __restrict__ A,
                                             const float* __restrict__ W,
                                             float* __restrict__ C,
                                             int M, int N, int K) {
    __shared__ __align__(16) float As[2][16][64];
    __shared__ __align__(16) float Bs[2][16][64];
    int tid = threadIdx.x;
    int tx = tid & 15, ty = tid >> 4;
    int tilesN = N >> 6;
    int m0 = (blockIdx.x / tilesN) << 6;
    int n0 = (blockIdx.x % tilesN) << 6;

    int ra = tid >> 2, ca = (tid & 3) << 2;
    int rb = tid >> 4, cb = (tid & 15) << 2;
    const float* Ap = A + (size_t)(m0 + ra) * K + ca;
    const float* Wp = W + (size_t)rb * N + n0 + cb;

    unsigned long long acc[4][2];
#pragma unroll
    for (int i = 0; i < 4; i++) { acc[i][0] = 0ull; acc[i][1] = 0ull; }

    int nch = K >> 4;
    {
        float4 va = *reinterpret_cast<const float4*>(Ap);
        if (RIN) {
            va.x = fmaxf(va.x, 0.f); va.y = fmaxf(va.y, 0.f);
            va.z = fmaxf(va.z, 0.f); va.w = fmaxf(va.w, 0.f);
        }
        float4 vb = *reinterpret_cast<const float4*>(Wp);
        As[0][ca + 0][ra] = va.x; As[0][ca + 1][ra] = va.y;
        As[0][ca + 2][ra] = va.z; As[0][ca + 3][ra] = va.w;
        *reinterpret_cast<float4*>(&Bs[0][rb][cb]) = vb;
    }
    __syncthreads();

    for (int ch = 0; ch < nch; ch++) {
        int cur = ch & 1;
        float4 va, vb;
        if (ch + 1 < nch) {
            va = *reinterpret_cast<const float4*>(Ap + (ch + 1) * 16);
            vb = *reinterpret_cast<const float4*>(Wp + (size_t)(ch + 1) * 16 * N);
            if (RIN) {
                va.x = fmaxf(va.x, 0.f); va.y = fmaxf(va.y, 0.f);
                va.z = fmaxf(va.z, 0.f); va.w = fmaxf(va.w, 0.f);
            }
        }
#pragma unroll
        for (int k = 0; k < 16; k++) {
            float4 a4 = *reinterpret_cast<float4*>(&As[cur][k][ty * 4]);
            ulonglong2 b2 = *reinterpret_cast<ulonglong2*>(&Bs[cur][k][tx * 4]);
            unsigned long long a0 = pk2(a4.x), a1 = pk2(a4.y);
            unsigned long long a2 = pk2(a4.z), a3 = pk2(a4.w);
            ffma2(acc[0][0], a0, b2.x); ffma2(acc[0][1], a0, b2.y);
            ffma2(acc[1][0], a1, b2.x); ffma2(acc[1][1], a1, b2.y);
            ffma2(acc[2][0], a2, b2.x); ffma2(acc[2][1], a2, b2.y);
            ffma2(acc[3][0], a3, b2.x); ffma2(acc[3][1], a3, b2.y);
        }
        if (ch + 1 < nch) {
            int nxt = cur ^ 1;
            As[nxt][ca + 0][ra] = va.x; As[nxt][ca + 1][ra] = va.y;
            As[nxt][ca + 2][ra] = va.z; As[nxt][ca + 3][ra] = va.w;
            *reinterpret_cast<float4*>(&Bs[nxt][rb][cb]) = vb;
        }
        __syncthreads();
    }
#pragma unroll
    for (int i = 0; i < 4; i++) {
        float2 u0 = up2(acc[i][0]);
        float2 u1 = up2(acc[i][1]);
        float vals[4] = {u0.x, u0.y, u1.x, u1.y};
#pragma unroll
        for (int j = 0; j < 4; j++) {
            float v = vals[j];
            if (ROUT) v = fmaxf(v, 0.f);
            int m = m0 + ty * 4 + i;
            int n = n0 + tx * 4 + j;
            if (TST) {
                C[(((size_t)(m >> 5) * NH) + n) * Bz + (m & 31)] = v;  // [t][n][b]
            } else {
                C[(size_t)m * N + n] = v;
            }
        }
    }
}

__global__ void __launch_bounds__(256) k_gemm_s(const float* __restrict__ x,
                                                const float* __restrict__ Wi) {
    gemm_big_dev<true, true, false>(x, Wi, dS, T * Bz, NH, NIN);
}
__global__ void __launch_bounds__(256) k_gemm_z(const float* __restrict__ Wz) {
    gemm_big_dev<false, true, false>(dS, Wz, dZ, T * Bz, NH, NH);
}
__global__ void __launch_bounds__(256) k_gemm_zc(const float* __restrict__ Wc) {
    gemm_big_dev<false, false, true>(dZ, Wc, dZCt, T * Bz, NH, NH);
}

// ---------------- persistent recurrence kernel (full-K / narrow-N) ----------
// CTA bx owns j in [8bx, 8bx+8). W column slice resident in smem, duplicated
// as f32x2 pairs. A (full 1024x32 activation) streamed in 8 chunks of 128 k.
// Thread tile: 2 j x 8 b (4 b-packs), 32-way k-split, combine via scr.
struct SmemR {
    unsigned long long Wd[1024][8];   // 64 KB: Wd[k][c] = (W[k][j0+c], same)
    float Ach[2][128][36];            // 36 KB: staged A chunk (rows padded)
    float scr[32][264];               // 33.8 KB: k-split combine scratch
    float hts[8][32];                 // local Ht rows
};

__device__ __forceinline__ void load_wd(SmemR* sm, const float* __restrict__ W,
                                        int ldw, int j0) {
    int tid = threadIdx.x;
#pragma unroll
    for (int i = 0; i < 2; i++) {
        int k = tid + i * 512;
        float4 w0 = *reinterpret_cast<const float4*>(&W[(size_t)k * ldw + j0]);
        float4 w1 = *reinterpret_cast<const float4*>(&W[(size_t)k * ldw + j0 + 4]);
        ulonglong2 p;
        p.x = pk2(w0.x); p.y = pk2(w0.y);
        *reinterpret_cast<ulonglong2*>(&sm->Wd[k][0]) = p;
        p.x = pk2(w0.z); p.y = pk2(w0.w);
        *reinterpret_cast<ulonglong2*>(&sm->Wd[k][2]) = p;
        p.x = pk2(w1.x); p.y = pk2(w1.y);
        *reinterpret_cast<ulonglong2*>(&sm->Wd[k][4]) = p;
        p.x = pk2(w1.z); p.y = pk2(w1.w);
        *reinterpret_cast<ulonglong2*>(&sm->Wd[k][6]) = p;
    }
}

// full-K GEMM of resident Wd against streamed A[1024][32]; leaves per-ksub
// partials in scr (caller reduces). Ends fully synced.
__device__ __forceinline__ void fullk_gemm(SmemR* sm, const float* __restrict__ A) {
    int tid  = threadIdx.x;
    int ksub = tid >> 4;          // 0..31
    int slot = tid & 15;
    int jp   = slot & 3;          // j-pair 0..3  -> j = 2jp, 2jp+1
    int bq   = slot >> 2;         // 0..3         -> b = 8bq .. 8bq+7
    unsigned long long a0=0,a1=0,a2=0,a3=0,a4=0,a5=0,a6=0,a7=0;

    const float4* src = reinterpret_cast<const float4*>(A);
    {   // stage chunk 0
        float4 v0 = src[tid], v1 = src[tid + 512];
        *reinterpret_cast<float4*>(&sm->Ach[0][tid >> 3][(tid & 7) * 4]) = v0;
        *reinterpret_cast<float4*>(&sm->Ach[0][(tid + 512) >> 3][((tid + 512) & 7) * 4]) = v1;
    }
    __syncthreads();

#pragma unroll
    for (int ch = 0; ch < 8; ch++) {
        int cur = ch & 1;
        float4 v0, v1;
        if (ch < 7) {
            v0 = src[(ch + 1) * 1024 + tid];
            v1 = src[(ch + 1) * 1024 + tid + 512];
        }
        int kb = ksub * 4;
#pragma unroll
        for (int kk = 0; kk < 4; kk++) {
            int k = kb + kk;
            ulonglong2 wv = *reinterpret_cast<const ulonglong2*>(&sm->Wd[ch * 128 + k][jp * 2]);
            ulonglong2 av01 = *reinterpret_cast<const ulonglong2*>(&sm->Ach[cur][k][bq * 8]);
            ulonglong2 av23 = *reinterpret_cast<const ulonglong2*>(&sm->Ach[cur][k][bq * 8 + 4]);
            ffma2(a0, wv.x, av01.x); ffma2(a1, wv.x, av01.y);
            ffma2(a2, wv.x, av23.x); ffma2(a3, wv.x, av23.y);
            ffma2(a4, wv.y, av01.x); ffma2(a5, wv.y, av01.y);
            ffma2(a6, wv.y, av23.x); ffma2(a7, wv.y, av23.y);
        }
        if (ch < 7) {
            int nxt = cur ^ 1;
            *reinterpret_cast<float4*>(&sm->Ach[nxt][tid >> 3][(tid & 7) * 4]) = v0;
            *reinterpret_cast<float4*>(&sm->Ach[nxt][(tid + 512) >> 3][((tid + 512) & 7) * 4]) = v1;
        }
        __syncthreads();
    }
    // combine write: scr[ksub][j_local*32 + b]
    int jl = jp * 2, b0 = bq * 8;
    float2 u0 = up2(a0), u1 = up2(a1), u2 = up2(a2), u3 = up2(a3);
    float4 r0 = {u0.x, u0.y, u1.x, u1.y};
    float4 r1 = {u2.x, u2.y, u3.x, u3.y};
    *reinterpret_cast<float4*>(&sm->scr[ksub][jl * 32 + b0])     = r0;
    *reinterpret_cast<float4*>(&sm->scr[ksub][jl * 32 + b0 + 4]) = r1;
    float2 u4 = up2(a4), u5 = up2(a5), u6 = up2(a6), u7 = up2(a7);
    float4 r2 = {u4.x, u4.y, u5.x, u5.y};
    float4 r3 = {u6.x, u6.y, u7.x, u7.y};
    *reinterpret_cast<float4*>(&sm->scr[ksub][(jl + 1) * 32 + b0])     = r2;
    *reinterpret_cast<float4*>(&sm->scr[ksub][(jl + 1) * 32 + b0 + 4]) = r3;
    __syncthreads();
}

__device__ __forceinline__ float red_scr(SmemR* sm, int jl, int lane) {
    float s = 0.f;
#pragma unroll
    for (int ks = 0; ks < 32; ks++) s += sm->scr[ks][jl * 32 + lane];
    return s;
}

__global__ void __launch_bounds__(NTH, 1)
memnet_rec_kernel(const float* __restrict__ Wh,  const float* __restrict__ Who,
                  const float* __restrict__ Wo,  const float* __restrict__ lam_p,
                  const float* __restrict__ eta_p, const float* __restrict__ g_p,
                  const float* __restrict__ b_p, float* __restrict__ out) {
    extern __shared__ __align__(16) char smembuf[];
    SmemR* sm = reinterpret_cast<SmemR*>(smembuf);
    int bx   = blockIdx.x;
    int tid  = threadIdx.x;
    int lane = tid & 31;
    int w    = tid >> 5;
    int j0   = bx * 8;

    load_wd(sm, Wh, NH, j0);
    if (bx == 0) {                       // zero both dot parity buffers
        float4 z = {0.f, 0.f, 0.f, 0.f};
        reinterpret_cast<float4*>(dDot2)[tid] = z;
    }
    gsync();

    const float lam = lam_p[0];
    const float eta = eta_p[0];

    for (int t = 0; t < T; t++) {
        const float* zc = dZCt + (size_t)t * NH * Bz;
        float* dbuf = dDot2 + (t & 1) * (T * Bz);

        // ---- P1: Ht = relu(zc + h_prev @ Wh) for own 8 rows; dot partials --
        if (t > 0) fullk_gemm(sm, dHcur);
        if (w < 8) {
            int jg = j0 + w;
            float v = zc[jg * Bz + lane];
            if (t > 0) v += red_scr(sm, w, lane);
            v = fmaxf(v, 0.f);
            sm->hts[w][lane] = v;
            dHist[(size_t)t * NH * Bz + (size_t)jg * Bz + lane] = v;
        }
        __syncthreads();
        for (int tau = w; tau <= t; tau += 16) {
            float c = 0.f;
            if (tau == t) {
#pragma unroll
                for (int r = 0; r < 8; r++) {
                    float h = sm->hts[r][lane];
                    c += h * h;
                }
            } else {
                const float* Hs = dHist + (size_t)tau * NH * Bz + (size_t)j0 * Bz;
#pragma unroll
                for (int r = 0; r < 8; r++)
                    c += sm->hts[r][lane] * Hs[r * Bz + lane];
            }
            atomicAdd(&dbuf[tau * Bz + lane], c);
        }
        gsync();

        // ---- P2: hs = Ht@Wh + zc + mem-term; local batchnorm -> dHcur ------
        fullk_gemm(sm, dHist + (size_t)t * NH * Bz);
        if (w < 8) {
            int jg = j0 + w;
            float acc = red_scr(sm, w, lane) + zc[jg * Bz + lane];
            float sc = eta;
#pragma unroll 4
            for (int tau = t; tau >= 0; tau--) {
                acc += sc * dbuf[tau * Bz + lane]
                          * dHist[(size_t)tau * NH * Bz + (size_t)jg * Bz + lane];
                sc *= lam;
            }
            float mu = acc;
#pragma unroll
            for (int o = 16; o > 0; o >>= 1) mu += __shfl_xor_sync(0xffffffffu, mu, o);
            mu *= (1.f / 32.f);
            float dv = acc - mu;
            float vv = dv * dv;
#pragma unroll
            for (int o = 16; o > 0; o >>= 1) vv += __shfl_xor_sync(0xffffffffu, vv, o);
            float rs = rsqrtf(vv * (1.f / 32.f));
            dHcur[(size_t)jg * Bz + lane] = fmaxf(g_p[jg] * dv * rs + b_p[jg], 0.f);
        } else if (bx == 0) {
            // warps 8-15: zero next parity's dot buffer (1024 floats)
            float4 z = {0.f, 0.f, 0.f, 0.f};
            reinterpret_cast<float4*>(dDot2 + ((t + 1) & 1) * (T * Bz))[(w - 8) * 32 + lane] = z;
        }
        gsync();
    }

    // ---- head1: o = relu(h @ W_ho), own 8 rows ----
    load_wd(sm, Who, NH, j0);
    fullk_gemm(sm, dHcur);
    if (w < 8) {
        float o = fmaxf(red_scr(sm, w, lane), 0.f);
        dOt[(size_t)(j0 + w) * Bz + lane] = o;
    }
    gsync();

    // ---- head2: y = relu(o @ W_o), 32 CTAs x 8 output cols ----
    if (bx < 32) {
        int j02 = bx * 8;
        load_wd(sm, Wo, NOUT, j02);
        fullk_gemm(sm, dOt);
        if (w < 8) {
            float y = fmaxf(red_scr(sm, w, lane), 0.f);
            out[(size_t)lane * NOUT + j02 + w] = y;
        }
    }
}

extern "C" void kernel_launch(void* const* d_in, const int* in_sizes, int n_in,
                              void* d_out, int out_size) {
    (void)in_sizes; (void)n_in; (void)out_size;
    const float* x   = (const float*)d_in[0];
    const float* Wi  = (const float*)d_in[1];
    const float* Wz  = (const float*)d_in[2];
    const float* Wc  = (const float*)d_in[3];
    const float* Wh  = (const float*)d_in[4];
    const float* Who = (const float*)d_in[5];
    const float* Wo  = (const float*)d_in[6];
    const float* lam = (const float*)d_in[7];
    const float* eta = (const float*)d_in[8];
    const float* g   = (const float*)d_in[9];
    const float* b   = (const float*)d_in[10];

    cudaFuncSetAttribute(memnet_rec_kernel,
                         cudaFuncAttributeMaxDynamicSharedMemorySize,
                         (int)sizeof(SmemR));

    k_gemm_s<<<256, 256>>>(x, Wi);
    k_gemm_z<<<256, 256>>>(Wz);
    k_gemm_zc<<<256, 256>>>(Wc);
    memnet_rec_kernel<<<NBLK, NTH, sizeof(SmemR)>>>(Wh, Who, Wo, lam, eta, g, b,
                                                    (float*)d_out);
}

// round 17
// speedup vs baseline: 1.2084x; 1.0138x over previous
#include <cuda_runtime.h>
#include <math.h>

#define T    32
#define Bz   32
#define NIN  512
#define NH   1024
#define NOUT 256
#define NBLK 128      // CTA bx owns output columns [8bx, 8bx+8); group g = bx>>4
#define NTH  512

// ---------------- persistent state (device globals; no allocation) ----------
__device__ float dS[T * Bz * NH];       // relu(relu(x)@W_i)      [m=(t,b)][k]
__device__ float dZ[T * Bz * NH];       // relu(S@W_z)            [m][k]
__device__ float dZCt[T * NH * Bz];     // Z@W_c transposed       [t][j][b]
__device__ float dHist[T * NH * Bz];    // h_t history (post-relu) [t][j][b]
__device__ float dHcur2[2 * NH * Bz];   // parity-buffered carry  [p][j][b]
__device__ float dOt[NH * Bz];          // o = relu(h@W_ho)       [j][b]
__device__ float dDot2[2 * T * Bz];     // parity-buffered dot accumulators
// producer/consumer flags (monotonic within launch; reset at kernel end)
__device__ unsigned fHtC[8 * 32];       // per-chunk Ht publishes (stride 128B)
__device__ unsigned fHcC[8 * 32];       // per-chunk h_next publishes
__device__ unsigned fDot;               // per-CTA dot publishes
// tree barrier (monotonic counters; zero-init once; graph-replay safe)
__device__ unsigned gLeaf[16 * 32];
__device__ unsigned gRoot;
__device__ volatile unsigned gEpoch;

// ---------------- packed f32x2 helpers --------------------------------------
static __device__ __forceinline__ unsigned long long pk2(float v) {
    unsigned long long r;
    asm("mov.b64 %0, {%1, %1};" : "=l"(r) : "f"(v));
    return r;
}
static __device__ __forceinline__ void ffma2(unsigned long long& d,
                                             unsigned long long a,
                                             unsigned long long b) {
    asm("fma.rn.f32x2 %0, %1, %2, %0;" : "+l"(d) : "l"(a), "l"(b));
}
static __device__ __forceinline__ float2 up2(unsigned long long v) {
    float2 f;
    asm("mov.b64 {%0, %1}, %2;" : "=f"(f.x), "=f"(f.y) : "l"(v));
    return f;
}

// ---------------- flag primitives -------------------------------------------
static __device__ __forceinline__ void spin_acq(const unsigned* p, unsigned tgt) {
    unsigned v;
    asm volatile("ld.acquire.gpu.global.u32 %0, [%1];" : "=r"(v) : "l"(p) : "memory");
    while (v < tgt) {
        __nanosleep(32);
        asm volatile("ld.acquire.gpu.global.u32 %0, [%1];" : "=r"(v) : "l"(p) : "memory");
    }
}
// call AFTER __syncthreads(), thread 0 only
static __device__ __forceinline__ void pub(unsigned* p) {
    __threadfence();
    atomicAdd(p, 1u);
}

// ---------------- tree grid barrier (used only outside the hot loop) --------
__device__ __forceinline__ void gsync() {
    __syncthreads();
    if (threadIdx.x == 0) {
        __threadfence();
        unsigned e = gEpoch;
        if ((atomicAdd(&gLeaf[((unsigned)blockIdx.x >> 3) << 5], 1u) & 7u) == 7u) {
            if ((atomicAdd(&gRoot, 1u) & 15u) == 15u) {
                __threadfence();
                atomicAdd((unsigned*)&gEpoch, 1u);
            }
        }
        while (gEpoch == e) {}
        __threadfence();
    }
    __syncthreads();
}

// ---------------- big GEMM (precompute): C[M,N] = op(A[M,K] @ W[K,N]) -------
template <bool RIN, bool ROUT, bool TST>
__device__ __forceinline__ void gemm_big_dev(const float* __restrict__ A,
                                             const float* __restrict__ W,
                                             float* __restrict__ C,
                                             int M, int N, int K) {
    __shared__ __align__(16) float As[2][16][64];
    __shared__ __align__(16) float Bs[2][16][64];
    int tid = threadIdx.x;
    int tx = tid & 15, ty = tid >> 4;
    int tilesN = N >> 6;
    int m0 = (blockIdx.x / tilesN) << 6;
    int n0 = (blockIdx.x % tilesN) << 6;

    int ra = tid >> 2, ca = (tid & 3) << 2;
    int rb = tid >> 4, cb = (tid & 15) << 2;
    const float* Ap = A + (size_t)(m0 + ra) * K + ca;
    const float* Wp = W + (size_t)rb * N + n0 + cb;

    unsigned long long acc[4][2];
#pragma unroll
    for (int i = 0; i < 4; i++) { acc[i][0] = 0ull; acc[i][1] = 0ull; }

    int nch = K >> 4;
    {
        float4 va = *reinterpret_cast<const float4*>(Ap);
        if (RIN) {
            va.x = fmaxf(va.x, 0.f); va.y = fmaxf(va.y, 0.f);
            va.z = fmaxf(va.z, 0.f); va.w = fmaxf(va.w, 0.f);
        }
        float4 vb = *reinterpret_cast<const float4*>(Wp);
        As[0][ca + 0][ra] = va.x; As[0][ca + 1][ra] = va.y;
        As[0][ca + 2][ra] = va.z; As[0][ca + 3][ra] = va.w;
        *reinterpret_cast<float4*>(&Bs[0][rb][cb]) = vb;
    }
    __syncthreads();

    for (int ch = 0; ch < nch; ch++) {
        int cur = ch & 1;
        float4 va, vb;
        if (ch + 1 < nch) {
            va = *reinterpret_cast<const float4*>(Ap + (ch + 1) * 16);
            vb = *reinterpret_cast<const float4*>(Wp + (size_t)(ch + 1) * 16 * N);
            if (RIN) {
                va.x = fmaxf(va.x, 0.f); va.y = fmaxf(va.y, 0.f);
                va.z = fmaxf(va.z, 0.f); va.w = fmaxf(va.w, 0.f);
            }
        }
#pragma unroll
        for (int k = 0; k < 16; k++) {
            float4 a4 = *reinterpret_cast<float4*>(&As[cur][k][ty * 4]);
            ulonglong2 b2 = *reinterpret_cast<ulonglong2*>(&Bs[cur][k][tx * 4]);
            unsigned long long a0 = pk2(a4.x), a1 = pk2(a4.y);
            unsigned long long a2 = pk2(a4.z), a3 = pk2(a4.w);
            ffma2(acc[0][0], a0, b2.x); ffma2(acc[0][1], a0, b2.y);
            ffma2(acc[1][0], a1, b2.x); ffma2(acc[1][1], a1, b2.y);
            ffma2(acc[2][0], a2, b2.x); ffma2(acc[2][1], a2, b2.y);
            ffma2(acc[3][0], a3, b2.x); ffma2(acc[3][1], a3, b2.y);
        }
        if (ch + 1 < nch) {
            int nxt = cur ^ 1;
            As[nxt][ca + 0][ra] = va.x; As[nxt][ca + 1][ra] = va.y;
            As[nxt][ca + 2][ra] = va.z; As[nxt][ca + 3][ra] = va.w;
            *reinterpret_cast<float4*>(&Bs[nxt][rb][cb]) = vb;
        }
        __syncthreads();
    }
#pragma unroll
    for (int i = 0; i < 4; i++) {
        float2 u0 = up2(acc[i][0]);
        float2 u1 = up2(acc[i][1]);
        float vals[4] = {u0.x, u0.y, u1.x, u1.y};
#pragma unroll
        for (int j = 0; j < 4; j++) {
            float v = vals[j];
            if (ROUT) v = fmaxf(v, 0.f);
            int m = m0 + ty * 4 + i;
            int n = n0 + tx * 4 + j;
            if (TST) {
                C[(((size_t)(m >> 5) * NH) + n) * Bz + (m & 31)] = v;  // [t][n][b]
            } else {
                C[(size_t)m * N + n] = v;
            }
        }
    }
}

__global__ void __launch_bounds__(256) k_gemm_s(const float* __restrict__ x,
                                                const float* __restrict__ Wi) {
    gemm_big_dev<true, true, false>(x, Wi, dS, T * Bz, NH, NIN);
}
__global__ void __launch_bounds__(256) k_gemm_z(const float* __restrict__ Wz) {
    gemm_big_dev<false, true, false>(dS, Wz, dZ, T * Bz, NH, NH);
}
__global__ void __launch_bounds__(256) k_gemm_zc(const float* __restrict__ Wc) {
    gemm_big_dev<false, false, true>(dZ, Wc, dZCt, T * Bz, NH, NH);
}

// ---------------- persistent recurrence kernel (pipelined dataflow) ---------
struct SmemR {
    unsigned long long Wd[1024][8];   // 64 KB: Wd[k][c] = (W[k][j0+c], same)
    float Ach[2][128][36];            // staged A chunk (rows padded)
    float scr[32][264];               // k-split combine scratch
    float hts[8][32];                 // local Ht rows
};

__device__ __forceinline__ void load_wd(SmemR* sm, const float* __restrict__ W,
                                        int ldw, int j0) {
    int tid = threadIdx.x;
#pragma unroll
    for (int i = 0; i < 2; i++) {
        int k = tid + i * 512;
        float4 w0 = *reinterpret_cast<const float4*>(&W[(size_t)k * ldw + j0]);
        float4 w1 = *reinterpret_cast<const float4*>(&W[(size_t)k * ldw + j0 + 4]);
        ulonglong2 p;
        p.x = pk2(w0.x); p.y = pk2(w0.y);
        *reinterpret_cast<ulonglong2*>(&sm->Wd[k][0]) = p;
        p.x = pk2(w0.z); p.y = pk2(w0.w);
        *reinterpret_cast<ulonglong2*>(&sm->Wd[k][2]) = p;
        p.x = pk2(w1.x); p.y = pk2(w1.y);
        *reinterpret_cast<ulonglong2*>(&sm->Wd[k][4]) = p;
        p.x = pk2(w1.z); p.y = pk2(w1.w);
        *reinterpret_cast<ulonglong2*>(&sm->Wd[k][6]) = p;
    }
}

// full-K GEMM with per-chunk flag gating and rotated chunk order (start = g).
// flags == nullptr -> no gating. Leaves per-ksub partials in scr; ends synced.
__device__ __forceinline__ void fullk_gemm_f(SmemR* sm, const float* __restrict__ A,
                                             const unsigned* flags, unsigned tgt,
                                             int g) {
    int tid  = threadIdx.x;
    int ksub = tid >> 4;          // 0..31
    int slot = tid & 15;
    int jp   = slot & 3;
    int bq   = slot >> 2;
    unsigned long long a0=0,a1=0,a2=0,a3=0,a4=0,a5=0,a6=0,a7=0;

    const float4* src = reinterpret_cast<const float4*>(A);
    int c0 = g & 7;
    if (flags) spin_acq(flags + (c0 << 5), tgt);
    {
        float4 v0 = src[c0 * 1024 + tid], v1 = src[c0 * 1024 + tid + 512];
        *reinterpret_cast<float4*>(&sm->Ach[0][tid >> 3][(tid & 7) * 4]) = v0;
        *reinterpret_cast<float4*>(&sm->Ach[0][(tid + 512) >> 3][((tid + 512) & 7) * 4]) = v1;
    }
    __syncthreads();

#pragma unroll
    for (int i = 0; i < 8; i++) {
        int cur = i & 1;
        int c   = (g + i) & 7;
        float4 v0, v1;
        if (i < 7) {
            int cn = (g + i + 1) & 7;
            if (flags) spin_acq(flags + (cn << 5), tgt);
            v0 = src[cn * 1024 + tid];
            v1 = src[cn * 1024 + tid + 512];
        }
        int kb = ksub * 4;
#pragma unroll
        for (int kk = 0; kk < 4; kk++) {
            int k = kb + kk;
            ulonglong2 wv   = *reinterpret_cast<const ulonglong2*>(&sm->Wd[c * 128 + k][jp * 2]);
            ulonglong2 av01 = *reinterpret_cast<const ulonglong2*>(&sm->Ach[cur][k][bq * 8]);
            ulonglong2 av23 = *reinterpret_cast<const ulonglong2*>(&sm->Ach[cur][k][bq * 8 + 4]);
            ffma2(a0, wv.x, av01.x); ffma2(a1, wv.x, av01.y);
            ffma2(a2, wv.x, av23.x); ffma2(a3, wv.x, av23.y);
            ffma2(a4, wv.y, av01.x); ffma2(a5, wv.y, av01.y);
            ffma2(a6, wv.y, av23.x); ffma2(a7, wv.y, av23.y);
        }
        if (i < 7) {
            int nxt = cur ^ 1;
            *reinterpret_cast<float4*>(&sm->Ach[nxt][tid >> 3][(tid & 7) * 4]) = v0;
            *reinterpret_cast<float4*>(&sm->Ach[nxt][(tid + 512) >> 3][((tid + 512) & 7) * 4]) = v1;
        }
        __syncthreads();
    }
    int jl = jp * 2, b0 = bq * 8;
    float2 u0 = up2(a0), u1 = up2(a1), u2 = up2(a2), u3 = up2(a3);
    float4 r0 = {u0.x, u0.y, u1.x, u1.y};
    float4 r1 = {u2.x, u2.y, u3.x, u3.y};
    *reinterpret_cast<float4*>(&sm->scr[ksub][jl * 32 + b0])     = r0;
    *reinterpret_cast<float4*>(&sm->scr[ksub][jl * 32 + b0 + 4]) = r1;
    float2 u4 = up2(a4), u5 = up2(a5), u6 = up2(a6), u7 = up2(a7);
    float4 r2 = {u4.x, u4.y, u5.x, u5.y};
    float4 r3 = {u6.x, u6.y, u7.x, u7.y};
    *reinterpret_cast<float4*>(&sm->scr[ksub][(jl + 1) * 32 + b0])     = r2;
    *reinterpret_cast<float4*>(&sm->scr[ksub][(jl + 1) * 32 + b0 + 4]) = r3;
    __syncthreads();
}

__device__ __forceinline__ float red_scr(SmemR* sm, int jl, int lane) {
    float s = 0.f;
#pragma unroll
    for (int ks = 0; ks < 32; ks++) s += sm->scr[ks][jl * 32 + lane];
    return s;
}

__global__ void __launch_bounds__(NTH, 1)
memnet_rec_kernel(const float* __restrict__ Wh,  const float* __restrict__ Who,
                  const float* __restrict__ Wo,  const float* __restrict__ lam_p,
                  const float* __restrict__ eta_p, const float* __restrict__ g_p,
                  const float* __restrict__ b_p, float* __restrict__ out) {
    extern __shared__ __align__(16) char smembuf[];
    SmemR* sm = reinterpret_cast<SmemR*>(smembuf);
    int bx   = blockIdx.x;
    int tid  = threadIdx.x;
    int lane = tid & 31;
    int w    = tid >> 5;
    int j0   = bx * 8;
    int g    = bx >> 4;                  // chunk group this CTA produces

    load_wd(sm, Wh, NH, j0);
    if (bx == 0) {                       // zero both dot parity buffers
        float4 z = {0.f, 0.f, 0.f, 0.f};
        reinterpret_cast<float4*>(dDot2)[tid] = z;
    }
    gsync();

    const float lam = lam_p[0];
    const float eta = eta_p[0];

    for (int t = 0; t < T; t++) {
        const float* zc = dZCt + (size_t)t * NH * Bz;
        float* dbuf = dDot2 + (t & 1) * (T * Bz);

        // ---- P1: Ht = relu(zc + h_prev @ Wh) own rows; publish; dots -------
        if (t > 0)
            fullk_gemm_f(sm, dHcur2 + (size_t)((t - 1) & 1) * NH * Bz,
                         fHcC, 16u * t, g);
        if (w < 8) {
            int jg = j0 + w;
            float v = zc[jg * Bz + lane];
            if (t > 0) v += red_scr(sm, w, lane);
            v = fmaxf(v, 0.f);
            sm->hts[w][lane] = v;
            dHist[(size_t)t * NH * Bz + (size_t)jg * Bz + lane] = v;
        }
        __syncthreads();
        if (tid == 0) pub(&fHtC[g << 5]);          // Ht chunk published early

        for (int tau = w; tau <= t; tau += 16) {
            float c = 0.f;
            if (tau == t) {
#pragma unroll
                for (int r = 0; r < 8; r++) {
                    float h = sm->hts[r][lane];
                    c += h * h;
                }
            } else {
                const float* Hs = dHist + (size_t)tau * NH * Bz + (size_t)j0 * Bz;
#pragma unroll
                for (int r = 0; r < 8; r++)
                    c += sm->hts[r][lane] * Hs[r * Bz + lane];
            }
            atomicAdd(&dbuf[tau * Bz + lane], c);
        }
        __syncthreads();
        if (tid == 0) pub(&fDot);

        // ---- P2: hs = Ht@Wh + zc + mem-term; local batchnorm; publish ------
        fullk_gemm_f(sm, dHist + (size_t)t * NH * Bz, fHtC, 16u * (t + 1), g);
        if (w < 8) {
            int jg = j0 + w;
            float acc = red_scr(sm, w, lane) + zc[jg * Bz + lane];
            spin_acq(&fDot, 128u * (t + 1));       // dots complete (overlapped)
            float sc = eta;
#pragma unroll 4
            for (int tau = t; tau >= 0; tau--) {
                acc += sc * dbuf[tau * Bz + lane]
                          * dHist[(size_t)tau * NH * Bz + (size_t)jg * Bz + lane];
                sc *= lam;
            }
            float mu = acc;
#pragma unroll
            for (int o = 16; o > 0; o >>= 1) mu += __shfl_xor_sync(0xffffffffu, mu, o);
            mu *= (1.f / 32.f);
            float dv = acc - mu;
            float vv = dv * dv;
#pragma unroll
            for (int o = 16; o > 0; o >>= 1) vv += __shfl_xor_sync(0xffffffffu, vv, o);
            float rs = rsqrtf(vv * (1.f / 32.f));
            dHcur2[(size_t)(t & 1) * NH * Bz + (size_t)jg * Bz + lane] =
                fmaxf(g_p[jg] * dv * rs + b_p[jg], 0.f);
        } else if (bx == 0) {
            // warps 8-15 of CTA 0: zero next parity's dot buffer (safe: all
            // readers of that parity finished before this CTA passed P1's wait)
            float4 z = {0.f, 0.f, 0.f, 0.f};
            reinterpret_cast<float4*>(dDot2 + ((t + 1) & 1) * (T * Bz))[(w - 8) * 32 + lane] = z;
        }
        __syncthreads();
        if (tid == 0) pub(&fHcC[g << 5]);
    }

    // ---- head1: o = relu(h @ W_ho), own 8 rows ----
    load_wd(sm, Who, NH, j0);
    fullk_gemm_f(sm, dHcur2 + (size_t)((T - 1) & 1) * NH * Bz,
                 fHcC, 16u * T, g);
    if (w < 8) {
        float o = fmaxf(red_scr(sm, w, lane), 0.f);
        dOt[(size_t)(j0 + w) * Bz + lane] = o;
    }
    gsync();                                       // dOt complete; flags idle

    // reset flags for the next graph replay (no flag reads after the gsync)
    if (bx == 0 && tid == 0) {
#pragma unroll
        for (int i = 0; i < 8; i++) { fHtC[i << 5] = 0u; fHcC[i << 5] = 0u; }
        fDot = 0u;
    }

    // ---- head2: y = relu(o @ W_o), 32 CTAs x 8 output cols ----
    if (bx < 32) {
        int j02 = bx * 8;
        load_wd(sm, Wo, NOUT, j02);
        fullk_gemm_f(sm, dOt, 0, 0u, bx & 7);
        if (w < 8) {
            float y = fmaxf(red_scr(sm, w, lane), 0.f);
            out[(size_t)lane * NOUT + j02 + w] = y;
        }
    }
}

extern "C" void kernel_launch(void* const* d_in, const int* in_sizes, int n_in,
                              void* d_out, int out_size) {
    (void)in_sizes; (void)n_in; (void)out_size;
    const float* x   = (const float*)d_in[0];
    const float* Wi  = (const float*)d_in[1];
    const float* Wz  = (const float*)d_in[2];
    const float* Wc  = (const float*)d_in[3];
    const float* Wh  = (const float*)d_in[4];
    const float* Who = (const float*)d_in[5];
    const float* Wo  = (const float*)d_in[6];
    const float* lam = (const float*)d_in[7];
    const float* eta = (const float*)d_in[8];
    const float* g   = (const float*)d_in[9];
    const float* b   = (const float*)d_in[10];

    cudaFuncSetAttribute(memnet_rec_kernel,
                         cudaFuncAttributeMaxDynamicSharedMemorySize,
                         (int)sizeof(SmemR));

    k_gemm_s<<<256, 256>>>(x, Wi);
    k_gemm_z<<<256, 256>>>(Wz);
    k_gemm_zc<<<256, 256>>>(Wc);
    memnet_rec_kernel<<<NBLK, NTH, sizeof(SmemR)>>>(Wh, Who, Wo, lam, eta, g, b,
                                                    (float*)d_out);
}